// round 4
// baseline (speedup 1.0000x reference)
#include <cuda_runtime.h>
#include <cstdint>

#define BB 4
#define SS 2048
#define DDIM 1024
#define HH 16
#define DKK 64
#define MTOT (BB*SS)   // 8192

// ---------------- scratch (static __device__, allocation-free) ----------------
__device__ float g_Q[(size_t)MTOT*DDIM];
__device__ float g_K[(size_t)MTOT*DDIM];
__device__ float g_V[(size_t)MTOT*DDIM];
__device__ float g_A[(size_t)MTOT*DDIM];

// ---------------- helpers ----------------
__device__ __forceinline__ uint32_t f2tf32(float f) {
    uint32_t u;
    asm("cvt.rna.tf32.f32 %0, %1;" : "=r"(u) : "f"(f));
    return u;
}
__device__ __forceinline__ float ex2(float x) {
    float y;
    asm("ex2.approx.ftz.f32 %0, %1;" : "=f"(y) : "f"(x));
    return y;
}
__device__ __forceinline__ void cp16(uint32_t saddr, const void* g) {
    asm volatile("cp.async.cg.shared.global [%0], [%1], 16;" :: "r"(saddr), "l"(g));
}
__device__ __forceinline__ void cp4(uint32_t saddr, const void* g) {
    asm volatile("cp.async.ca.shared.global [%0], [%1], 4;" :: "r"(saddr), "l"(g));
}
__device__ __forceinline__ void cp_commit() {
    asm volatile("cp.async.commit_group;");
}
template <int N>
__device__ __forceinline__ void cp_wait() {
    asm volatile("cp.async.wait_group %0;" :: "n"(N));
}

// D(16x8,f32) += A(16x8,tf32,row) * B(8x8,tf32,col)
__device__ __forceinline__ void mma_tf32(float c[4],
                                         uint32_t a0, uint32_t a1, uint32_t a2, uint32_t a3,
                                         uint32_t b0, uint32_t b1) {
    asm volatile(
        "mma.sync.aligned.m16n8k8.row.col.f32.tf32.tf32.f32 "
        "{%0,%1,%2,%3}, {%4,%5,%6,%7}, {%8,%9}, {%0,%1,%2,%3};"
        : "+f"(c[0]), "+f"(c[1]), "+f"(c[2]), "+f"(c[3])
        : "r"(a0), "r"(a1), "r"(a2), "r"(a3), "r"(b0), "r"(b1));
}

// ---------------- GEMM: C[m][n] = sum_k A[m][k] * W[n][k] ----------------
// block 128x256, warp 64x64 (2x4 warp grid), 2-stage cp.async, GBK=32
#define GBM 128
#define GBN 256
#define GBK 32
#define GST (GBK + 4)                         // 36-float row stride
#define GASTG (GBM * GST)                     // A floats/stage
#define GBSTG (GBN * GST)                     // B floats/stage
#define GSMEM ((2 * GASTG + 2 * GBSTG) * 4)   // 110592 B

__global__ __launch_bounds__(256, 1)
void gemm_nt(const float* __restrict__ A0, const float* __restrict__ A1, const float* __restrict__ A2,
             const float* __restrict__ W0, const float* __restrict__ W1, const float* __restrict__ W2,
             float* __restrict__ C0, float* __restrict__ C1, float* __restrict__ C2) {
    extern __shared__ float gsm[];
    float* Asm = gsm;                   // 2 stages of [GBM][GST]
    float* Bsm = gsm + 2 * GASTG;       // 2 stages of [GBN][GST]

    const int z = blockIdx.z;
    const float* A = (z == 0) ? A0 : (z == 1) ? A1 : A2;
    const float* W = (z == 0) ? W0 : (z == 1) ? W1 : W2;
    float*       C = (z == 0) ? C0 : (z == 1) ? C1 : C2;

    const int m0 = blockIdx.y * GBM;
    const int n0 = blockIdx.x * GBN;
    const int tid = threadIdx.x;
    const int w = tid >> 5, lane = tid & 31;
    const int g = lane >> 2, tig = lane & 3;
    const int wm = (w >> 2) * 64;   // 2 warp rows
    const int wn = (w & 3) * 64;    // 4 warp cols

    const uint32_t sA = (uint32_t)__cvta_generic_to_shared(Asm);
    const uint32_t sB = (uint32_t)__cvta_generic_to_shared(Bsm);

    float acc[4][8][4];
#pragma unroll
    for (int i = 0; i < 4; i++)
#pragma unroll
        for (int j = 0; j < 8; j++)
#pragma unroll
            for (int e = 0; e < 4; e++) acc[i][j][e] = 0.f;

    auto issue = [&](int st, int k0) {
#pragma unroll
        for (int t = 0; t < 4; t++) {          // A: 1024 float4
            int idx = tid + t * 256;
            int r = idx >> 3, ci = idx & 7;
            cp16(sA + (uint32_t)((st * GBM + r) * GST + ci * 4) * 4,
                 &A[(size_t)(m0 + r) * DDIM + k0 + ci * 4]);
        }
#pragma unroll
        for (int t = 0; t < 8; t++) {          // B: 2048 float4
            int idx = tid + t * 256;
            int r = idx >> 3, ci = idx & 7;
            cp16(sB + (uint32_t)((st * GBN + r) * GST + ci * 4) * 4,
                 &W[(size_t)(n0 + r) * DDIM + k0 + ci * 4]);
        }
    };

    issue(0, 0);
    cp_commit();

    const int NKT = DDIM / GBK;   // 32
    for (int kt = 0; kt < NKT; kt++) {
        const int cur = kt & 1;
        if (kt + 1 < NKT) {
            issue(cur ^ 1, (kt + 1) * GBK);
            cp_commit();
            cp_wait<1>();
        } else {
            cp_wait<0>();
        }
        __syncthreads();

        const float* Ac = Asm + cur * GASTG;
        const float* Bc = Bsm + cur * GBSTG;

#pragma unroll
        for (int ks = 0; ks < 4; ks++) {
            const int kk = ks * 8;
            uint32_t bfr[8][2];
#pragma unroll
            for (int nt = 0; nt < 8; nt++) {
                int n = wn + nt * 8 + g;
                bfr[nt][0] = f2tf32(Bc[n * GST + kk + tig]);
                bfr[nt][1] = f2tf32(Bc[n * GST + kk + tig + 4]);
            }
#pragma unroll
            for (int mt = 0; mt < 4; mt++) {
                int m = wm + mt * 16 + g;
                uint32_t a0 = f2tf32(Ac[m * GST + kk + tig]);
                uint32_t a1 = f2tf32(Ac[(m + 8) * GST + kk + tig]);
                uint32_t a2 = f2tf32(Ac[m * GST + kk + tig + 4]);
                uint32_t a3 = f2tf32(Ac[(m + 8) * GST + kk + tig + 4]);
#pragma unroll
                for (int nt = 0; nt < 8; nt++)
                    mma_tf32(acc[mt][nt], a0, a1, a2, a3, bfr[nt][0], bfr[nt][1]);
            }
        }
        __syncthreads();
    }

#pragma unroll
    for (int mt = 0; mt < 4; mt++) {
        int r0 = m0 + wm + mt * 16 + g;
#pragma unroll
        for (int nt = 0; nt < 8; nt++) {
            int col = n0 + wn + nt * 8 + 2 * tig;
            *reinterpret_cast<float2*>(&C[(size_t)r0 * DDIM + col]) =
                make_float2(acc[mt][nt][0], acc[mt][nt][1]);
            *reinterpret_cast<float2*>(&C[(size_t)(r0 + 8) * DDIM + col]) =
                make_float2(acc[mt][nt][2], acc[mt][nt][3]);
        }
    }
}

// ---------------- flash attention: 128-row Q tile, cp.async double-buffered K/V ----------------
#define AQT 128
#define AP 68
// smem: K[2][64*AP] + V[2][64*AP] + P[128*AP] floats + mask[2][64] ints
#define ASMEM ((2*64 + 2*64 + 128) * AP * 4 + 2 * 64 * 4)

__global__ __launch_bounds__(128, 1)
void attn_kernel(const float* __restrict__ Q, const float* __restrict__ K,
                 const float* __restrict__ V, const int* __restrict__ mask,
                 float* __restrict__ O) {
    extern __shared__ uint32_t smem_u[];
    uint32_t* Ks0 = smem_u;                     // 2 stages x 64 rows
    uint32_t* Vs0 = Ks0 + 2 * 64 * AP;
    uint32_t* Ps  = Vs0 + 2 * 64 * AP;          // 128 rows (also Q staging)
    int* msk0 = (int*)(Ps + 128 * AP);          // 2 stages x 64

    const int qi = blockIdx.x;                  // 0..15
    const int bh = blockIdx.y;                  // 0..63
    const int b = bh / HH, h = bh % HH;

    const int tid = threadIdx.x;
    const int w = tid >> 5, lane = tid & 31;
    const int g = lane >> 2, tig = lane & 3;
    const int wrow = w * 32;

    const float* Qb = Q + ((size_t)b * SS + (size_t)qi * AQT) * DDIM + h * DKK;
    const float* Kb = K + (size_t)b * SS * DDIM + h * DKK;
    const float* Vb = V + (size_t)b * SS * DDIM + h * DKK;
    float* Ob = O + ((size_t)b * SS + (size_t)qi * AQT) * DDIM + h * DKK;

    const uint32_t sK = (uint32_t)__cvta_generic_to_shared(Ks0);
    const uint32_t sV = (uint32_t)__cvta_generic_to_shared(Vs0);
    const uint32_t sM = (uint32_t)__cvta_generic_to_shared(msk0);

    const float qscale = 0.125f * 1.4426950408889634f;

    auto issueKV = [&](int st, int kt) {
        const float* Kt = Kb + (size_t)kt * 64 * DDIM;
        const float* Vt = Vb + (size_t)kt * 64 * DDIM;
#pragma unroll
        for (int t = 0; t < 8; t++) {
            int i = tid + t * 128;
            int r = i >> 4;
            int c4 = (i & 15) << 2;
            uint32_t off = (uint32_t)((st * 64 + r) * AP + c4) * 4;
            cp16(sK + off, Kt + (size_t)r * DDIM + c4);
            cp16(sV + off, Vt + (size_t)r * DDIM + c4);
        }
        if (tid < 64) cp4(sM + (uint32_t)(st * 64 + tid) * 4, &mask[(size_t)b * SS + kt * 64 + tid]);
    };

    const int ktmax = 2 * qi + 1;
    issueKV(0, 0);
    cp_commit();

    // stage Q (128x64) through Ps, then pull fragments into registers
#pragma unroll
    for (int t = 0; t < 16; t++) {
        int i = tid + t * 128;
        int r = i >> 4;
        int c4 = (i & 15) << 2;
        float4 v = *reinterpret_cast<const float4*>(Qb + (size_t)r * DDIM + c4);
        uint32_t* p = &Ps[r * AP + c4];
        p[0] = f2tf32(v.x * qscale); p[1] = f2tf32(v.y * qscale);
        p[2] = f2tf32(v.z * qscale); p[3] = f2tf32(v.w * qscale);
    }
    __syncthreads();

    uint32_t qf[2][8][4];
#pragma unroll
    for (int mt = 0; mt < 2; mt++) {
        int r = wrow + mt * 16;
#pragma unroll
        for (int ks = 0; ks < 8; ks++) {
            int kk = ks * 8;
            qf[mt][ks][0] = Ps[(r + g) * AP + kk + tig];
            qf[mt][ks][1] = Ps[(r + g + 8) * AP + kk + tig];
            qf[mt][ks][2] = Ps[(r + g) * AP + kk + tig + 4];
            qf[mt][ks][3] = Ps[(r + g + 8) * AP + kk + tig + 4];
        }
    }

    float mrow[2][2], lrow[2][2];
    float o[2][8][4];
#pragma unroll
    for (int mt = 0; mt < 2; mt++) {
        mrow[mt][0] = mrow[mt][1] = -1e30f;
        lrow[mt][0] = lrow[mt][1] = 0.f;
#pragma unroll
        for (int nt = 0; nt < 8; nt++)
#pragma unroll
            for (int e = 0; e < 4; e++) o[mt][nt][e] = 0.f;
    }

    const int rowmax = qi * AQT + wrow + 31;

    for (int kt = 0; kt <= ktmax; kt++) {
        const int cur = kt & 1;
        if (kt < ktmax) {
            issueKV(cur ^ 1, kt + 1);
            cp_commit();
            cp_wait<1>();
        } else {
            cp_wait<0>();
        }
        __syncthreads();

        // in-place convert stage cur: fp32 -> tf32 bits
        uint32_t* Ks = Ks0 + cur * 64 * AP;
        uint32_t* Vs = Vs0 + cur * 64 * AP;
        int* msk = msk0 + cur * 64;
#pragma unroll
        for (int t = 0; t < 8; t++) {
            int i = tid + t * 128;
            int r = i >> 4;
            int c4 = (i & 15) << 2;
            float4 vk = *reinterpret_cast<float4*>(&Ks[r * AP + c4]);
            uint4 uk = make_uint4(f2tf32(vk.x), f2tf32(vk.y), f2tf32(vk.z), f2tf32(vk.w));
            *reinterpret_cast<uint4*>(&Ks[r * AP + c4]) = uk;
            float4 vv = *reinterpret_cast<float4*>(&Vs[r * AP + c4]);
            uint4 uv = make_uint4(f2tf32(vv.x), f2tf32(vv.y), f2tf32(vv.z), f2tf32(vv.w));
            *reinterpret_cast<uint4*>(&Vs[r * AP + c4]) = uv;
        }
        __syncthreads();

        if (kt * 64 <= rowmax) {
            // S = Q @ K^T : 32x64 per warp (2 m-tiles)
            float s[2][8][4];
#pragma unroll
            for (int mt = 0; mt < 2; mt++)
#pragma unroll
                for (int nt = 0; nt < 8; nt++)
                    s[mt][nt][0] = s[mt][nt][1] = s[mt][nt][2] = s[mt][nt][3] = 0.f;

#pragma unroll
            for (int ks = 0; ks < 8; ks++) {
                int kk = ks * 8;
                uint32_t bf[8][2];
#pragma unroll
                for (int nt = 0; nt < 8; nt++) {
                    bf[nt][0] = Ks[(nt * 8 + g) * AP + kk + tig];
                    bf[nt][1] = Ks[(nt * 8 + g) * AP + kk + tig + 4];
                }
#pragma unroll
                for (int mt = 0; mt < 2; mt++)
#pragma unroll
                    for (int nt = 0; nt < 8; nt++)
                        mma_tf32(s[mt][nt], qf[mt][ks][0], qf[mt][ks][1],
                                 qf[mt][ks][2], qf[mt][ks][3], bf[nt][0], bf[nt][1]);
            }

#pragma unroll
            for (int mt = 0; mt < 2; mt++) {
                const int q0 = qi * AQT + wrow + mt * 16 + g;
                const int q1 = q0 + 8;
                const bool needc = (kt * 64 + 63 > qi * AQT + wrow + mt * 16);
#pragma unroll
                for (int nt = 0; nt < 8; nt++) {
                    int cl = nt * 8 + 2 * tig;
                    int cg = kt * 64 + cl;
                    bool mv0 = (msk[cl] != 0);
                    bool mv1 = (msk[cl + 1] != 0);
                    if (!mv0 || (needc && cg > q0))     s[mt][nt][0] = -1e30f;
                    if (!mv1 || (needc && cg + 1 > q0)) s[mt][nt][1] = -1e30f;
                    if (!mv0 || (needc && cg > q1))     s[mt][nt][2] = -1e30f;
                    if (!mv1 || (needc && cg + 1 > q1)) s[mt][nt][3] = -1e30f;
                }

                float rm0 = -1e30f, rm1 = -1e30f;
#pragma unroll
                for (int nt = 0; nt < 8; nt++) {
                    rm0 = fmaxf(rm0, fmaxf(s[mt][nt][0], s[mt][nt][1]));
                    rm1 = fmaxf(rm1, fmaxf(s[mt][nt][2], s[mt][nt][3]));
                }
                rm0 = fmaxf(rm0, __shfl_xor_sync(0xffffffffu, rm0, 1));
                rm0 = fmaxf(rm0, __shfl_xor_sync(0xffffffffu, rm0, 2));
                rm1 = fmaxf(rm1, __shfl_xor_sync(0xffffffffu, rm1, 1));
                rm1 = fmaxf(rm1, __shfl_xor_sync(0xffffffffu, rm1, 2));

                float mn0 = fmaxf(mrow[mt][0], rm0);
                float mn1 = fmaxf(mrow[mt][1], rm1);
                float al0 = ex2(mrow[mt][0] - mn0);
                float al1 = ex2(mrow[mt][1] - mn1);
                mrow[mt][0] = mn0; mrow[mt][1] = mn1;

                float rs0 = 0.f, rs1 = 0.f;
                const int pr = wrow + mt * 16;
#pragma unroll
                for (int nt = 0; nt < 8; nt++) {
                    int cl = nt * 8 + 2 * tig;
                    float p0 = ex2(s[mt][nt][0] - mn0);
                    float p1 = ex2(s[mt][nt][1] - mn0);
                    float p2 = ex2(s[mt][nt][2] - mn1);
                    float p3 = ex2(s[mt][nt][3] - mn1);
                    rs0 += p0 + p1;
                    rs1 += p2 + p3;
                    Ps[(pr + g) * AP + cl]         = f2tf32(p0);
                    Ps[(pr + g) * AP + cl + 1]     = f2tf32(p1);
                    Ps[(pr + g + 8) * AP + cl]     = f2tf32(p2);
                    Ps[(pr + g + 8) * AP + cl + 1] = f2tf32(p3);
                }
                rs0 += __shfl_xor_sync(0xffffffffu, rs0, 1);
                rs0 += __shfl_xor_sync(0xffffffffu, rs0, 2);
                rs1 += __shfl_xor_sync(0xffffffffu, rs1, 1);
                rs1 += __shfl_xor_sync(0xffffffffu, rs1, 2);
                lrow[mt][0] = lrow[mt][0] * al0 + rs0;
                lrow[mt][1] = lrow[mt][1] * al1 + rs1;

#pragma unroll
                for (int nt = 0; nt < 8; nt++) {
                    o[mt][nt][0] *= al0; o[mt][nt][1] *= al0;
                    o[mt][nt][2] *= al1; o[mt][nt][3] *= al1;
                }
            }
            __syncwarp();

            // O += P @ V
#pragma unroll
            for (int ks = 0; ks < 8; ks++) {
                int kk = ks * 8;
                uint32_t vb[8][2];
#pragma unroll
                for (int nt = 0; nt < 8; nt++) {
                    vb[nt][0] = Vs[(kk + tig) * AP + nt * 8 + g];
                    vb[nt][1] = Vs[(kk + tig + 4) * AP + nt * 8 + g];
                }
#pragma unroll
                for (int mt = 0; mt < 2; mt++) {
                    const int pr = wrow + mt * 16;
                    uint32_t a0 = Ps[(pr + g) * AP + kk + tig];
                    uint32_t a1 = Ps[(pr + g + 8) * AP + kk + tig];
                    uint32_t a2 = Ps[(pr + g) * AP + kk + tig + 4];
                    uint32_t a3 = Ps[(pr + g + 8) * AP + kk + tig + 4];
#pragma unroll
                    for (int nt = 0; nt < 8; nt++)
                        mma_tf32(o[mt][nt], a0, a1, a2, a3, vb[nt][0], vb[nt][1]);
                }
            }
        }
        __syncthreads();
    }

    // normalize + store
#pragma unroll
    for (int mt = 0; mt < 2; mt++) {
        float i0 = 1.f / lrow[mt][0];
        float i1 = 1.f / lrow[mt][1];
        int r0 = wrow + mt * 16 + g;
#pragma unroll
        for (int nt = 0; nt < 8; nt++) {
            int cl = nt * 8 + 2 * tig;
            *reinterpret_cast<float2*>(&Ob[(size_t)r0 * DDIM + cl]) =
                make_float2(o[mt][nt][0] * i0, o[mt][nt][1] * i0);
            *reinterpret_cast<float2*>(&Ob[(size_t)(r0 + 8) * DDIM + cl]) =
                make_float2(o[mt][nt][2] * i1, o[mt][nt][3] * i1);
        }
    }
}

// ---------------- launch ----------------
extern "C" void kernel_launch(void* const* d_in, const int* in_sizes, int n_in,
                              void* d_out, int out_size) {
    const float* xq = (const float*)d_in[0];
    const float* xk = (const float*)d_in[1];
    const float* xv = (const float*)d_in[2];
    const int* mask = (const int*)d_in[3];
    const float* Wq = (const float*)d_in[4];
    const float* Wk = (const float*)d_in[5];
    const float* Wv = (const float*)d_in[6];
    const float* Wo = (const float*)d_in[7];
    float* out = (float*)d_out;

    float *Qp, *Kp, *Vp, *Ap;
    cudaGetSymbolAddress((void**)&Qp, g_Q);
    cudaGetSymbolAddress((void**)&Kp, g_K);
    cudaGetSymbolAddress((void**)&Vp, g_V);
    cudaGetSymbolAddress((void**)&Ap, g_A);

    cudaFuncSetAttribute(gemm_nt, cudaFuncAttributeMaxDynamicSharedMemorySize, GSMEM);
    cudaFuncSetAttribute(attn_kernel, cudaFuncAttributeMaxDynamicSharedMemorySize, ASMEM);

    // fused QKV projections (gridDim.z selects the GEMM)
    gemm_nt<<<dim3(DDIM / GBN, MTOT / GBM, 3), 256, GSMEM>>>(
        xq, xk, xv, Wq, Wk, Wv, Qp, Kp, Vp);

    attn_kernel<<<dim3(SS / AQT, BB * HH), 128, ASMEM>>>(Qp, Kp, Vp, mask, Ap);

    gemm_nt<<<dim3(DDIM / GBN, MTOT / GBM, 1), 256, GSMEM>>>(
        Ap, Ap, Ap, Wo, Wo, Wo, out, out, out);
}

// round 5
// speedup vs baseline: 1.0392x; 1.0392x over previous
#include <cuda_runtime.h>
#include <cstdint>

#define BB 4
#define SS 2048
#define DDIM 1024
#define HH 16
#define DKK 64
#define MTOT (BB*SS)   // 8192

// ---------------- scratch (static __device__, allocation-free) ----------------
__device__ float g_Q[(size_t)MTOT*DDIM];
__device__ float g_K[(size_t)MTOT*DDIM];
__device__ float g_V[(size_t)MTOT*DDIM];
__device__ float g_A[(size_t)MTOT*DDIM];

// ---------------- helpers ----------------
__device__ __forceinline__ uint32_t f2tf32(float f) {
    uint32_t u;
    asm("cvt.rna.tf32.f32 %0, %1;" : "=r"(u) : "f"(f));
    return u;
}
__device__ __forceinline__ float ex2(float x) {
    float y;
    asm("ex2.approx.ftz.f32 %0, %1;" : "=f"(y) : "f"(x));
    return y;
}
__device__ __forceinline__ void cp16(uint32_t saddr, const void* g) {
    asm volatile("cp.async.cg.shared.global [%0], [%1], 16;" :: "r"(saddr), "l"(g));
}
__device__ __forceinline__ void cp4(uint32_t saddr, const void* g) {
    asm volatile("cp.async.ca.shared.global [%0], [%1], 4;" :: "r"(saddr), "l"(g));
}
__device__ __forceinline__ void cp_commit() {
    asm volatile("cp.async.commit_group;");
}
template <int N>
__device__ __forceinline__ void cp_wait() {
    asm volatile("cp.async.wait_group %0;" :: "n"(N));
}

// D(16x8,f32) += A(16x8,tf32,row) * B(8x8,tf32,col)
__device__ __forceinline__ void mma_tf32(float c[4],
                                         uint32_t a0, uint32_t a1, uint32_t a2, uint32_t a3,
                                         uint32_t b0, uint32_t b1) {
    asm volatile(
        "mma.sync.aligned.m16n8k8.row.col.f32.tf32.tf32.f32 "
        "{%0,%1,%2,%3}, {%4,%5,%6,%7}, {%8,%9}, {%0,%1,%2,%3};"
        : "+f"(c[0]), "+f"(c[1]), "+f"(c[2]), "+f"(c[3])
        : "r"(a0), "r"(a1), "r"(a2), "r"(a3), "r"(b0), "r"(b1));
}

// ---------------- GEMM: C[m][n] = sum_k A[m][k] * W[n][k] ----------------
// block 128x128, warp 64x32 (R2 config), 3-stage cp.async, GBK=32, one sync/iter
#define GBM 128
#define GBN 128
#define GBK 32
#define GST (GBK + 4)                         // 36-float row stride
#define GSTG (GBM * GST)                      // floats per stage per matrix
#define GNS 3
#define GSMEM (2 * GNS * GSTG * 4)            // 110592 B

__global__ __launch_bounds__(256, 1)
void gemm_nt(const float* __restrict__ A0, const float* __restrict__ A1, const float* __restrict__ A2,
             const float* __restrict__ W0, const float* __restrict__ W1, const float* __restrict__ W2,
             float* __restrict__ C0, float* __restrict__ C1, float* __restrict__ C2) {
    extern __shared__ float gsm[];
    float* Asm = gsm;                   // GNS stages of [GBM][GST]
    float* Bsm = gsm + GNS * GSTG;      // GNS stages of [GBN][GST]

    const int z = blockIdx.z;
    const float* A = (z == 0) ? A0 : (z == 1) ? A1 : A2;
    const float* W = (z == 0) ? W0 : (z == 1) ? W1 : W2;
    float*       C = (z == 0) ? C0 : (z == 1) ? C1 : C2;

    const int m0 = blockIdx.y * GBM;
    const int n0 = blockIdx.x * GBN;
    const int tid = threadIdx.x;
    const int w = tid >> 5, lane = tid & 31;
    const int g = lane >> 2, tig = lane & 3;
    const int wm = (w >> 2) * 64;   // 2 warp rows
    const int wn = (w & 3) * 32;    // 4 warp cols

    const int lr = tid >> 3;          // 0..31
    const int lc = (tid & 7) << 2;    // 0,4,..,28

    const uint32_t sA = (uint32_t)__cvta_generic_to_shared(Asm);
    const uint32_t sB = (uint32_t)__cvta_generic_to_shared(Bsm);

    float acc[4][4][4];
#pragma unroll
    for (int i = 0; i < 4; i++)
#pragma unroll
        for (int j = 0; j < 4; j++)
#pragma unroll
            for (int e = 0; e < 4; e++) acc[i][j][e] = 0.f;

    auto issue = [&](int st, int k0) {
#pragma unroll
        for (int it = 0; it < 4; it++) {
            int row = lr + it * 32;
            cp16(sA + (uint32_t)((st * GBM + row) * GST + lc) * 4,
                 &A[(size_t)(m0 + row) * DDIM + k0 + lc]);
            cp16(sB + (uint32_t)((st * GBN + row) * GST + lc) * 4,
                 &W[(size_t)(n0 + row) * DDIM + k0 + lc]);
        }
    };

    issue(0, 0); cp_commit();
    issue(1, GBK); cp_commit();

    const int NKT = DDIM / GBK;       // 32
    for (int kt = 0; kt < NKT; kt++) {
        if (kt < NKT - 1) cp_wait<1>(); else cp_wait<0>();
        __syncthreads();

        const int st = kt % GNS;
        const float* Ac = Asm + st * GSTG;
        const float* Bc = Bsm + st * GSTG;

#pragma unroll
        for (int ks = 0; ks < 4; ks++) {
            const int kk = ks * 8;
            uint32_t b[4][2];
#pragma unroll
            for (int nt = 0; nt < 4; nt++) {
                int n = wn + nt * 8 + g;
                b[nt][0] = f2tf32(Bc[n * GST + kk + tig]);
                b[nt][1] = f2tf32(Bc[n * GST + kk + tig + 4]);
            }
#pragma unroll
            for (int mt = 0; mt < 4; mt++) {
                int m = wm + mt * 16 + g;
                uint32_t a0 = f2tf32(Ac[m * GST + kk + tig]);
                uint32_t a1 = f2tf32(Ac[(m + 8) * GST + kk + tig]);
                uint32_t a2 = f2tf32(Ac[m * GST + kk + tig + 4]);
                uint32_t a3 = f2tf32(Ac[(m + 8) * GST + kk + tig + 4]);
#pragma unroll
                for (int nt = 0; nt < 4; nt++)
                    mma_tf32(acc[mt][nt], a0, a1, a2, a3, b[nt][0], b[nt][1]);
            }
        }

        // issue stage kt+2 (safe: its previous consumer was compute(kt-1),
        // and every warp passed this iteration's barrier after that)
        if (kt + 2 < NKT) {
            issue((kt + 2) % GNS, (kt + 2) * GBK);
            cp_commit();
        }
    }

#pragma unroll
    for (int mt = 0; mt < 4; mt++) {
        int r0 = m0 + wm + mt * 16 + g;
#pragma unroll
        for (int nt = 0; nt < 4; nt++) {
            int col = n0 + wn + nt * 8 + 2 * tig;
            *reinterpret_cast<float2*>(&C[(size_t)r0 * DDIM + col]) =
                make_float2(acc[mt][nt][0], acc[mt][nt][1]);
            *reinterpret_cast<float2*>(&C[(size_t)(r0 + 8) * DDIM + col]) =
                make_float2(acc[mt][nt][2], acc[mt][nt][3]);
        }
    }
}

// ---------------- flash attention: 128-row Q tile, cp.async K/V double-buffer,
// ---------------- cvt at fragment-load time (no smem convert pass) ----------------
#define AQT 128
#define AP 68
#define ASMEM ((2*64 + 2*64 + 128) * AP * 4 + 2 * 64 * 4)

__global__ __launch_bounds__(128, 1)
void attn_kernel(const float* __restrict__ Q, const float* __restrict__ K,
                 const float* __restrict__ V, const int* __restrict__ mask,
                 float* __restrict__ O) {
    extern __shared__ float smem_f[];
    float* Ks0 = smem_f;                       // 2 stages x 64 rows, raw fp32
    float* Vs0 = Ks0 + 2 * 64 * AP;
    uint32_t* Ps = (uint32_t*)(Vs0 + 2 * 64 * AP);   // 128 rows (also Q staging)
    int* msk0 = (int*)(Ps + 128 * AP);         // 2 stages x 64

    const int qi = blockIdx.x;                 // 0..15
    const int bh = blockIdx.y;                 // 0..63
    const int b = bh / HH, h = bh % HH;

    const int tid = threadIdx.x;
    const int w = tid >> 5, lane = tid & 31;
    const int g = lane >> 2, tig = lane & 3;
    const int wrow = w * 32;

    const float* Qb = Q + ((size_t)b * SS + (size_t)qi * AQT) * DDIM + h * DKK;
    const float* Kb = K + (size_t)b * SS * DDIM + h * DKK;
    const float* Vb = V + (size_t)b * SS * DDIM + h * DKK;
    float* Ob = O + ((size_t)b * SS + (size_t)qi * AQT) * DDIM + h * DKK;

    const uint32_t sK = (uint32_t)__cvta_generic_to_shared(Ks0);
    const uint32_t sV = (uint32_t)__cvta_generic_to_shared(Vs0);
    const uint32_t sM = (uint32_t)__cvta_generic_to_shared(msk0);

    const float qscale = 0.125f * 1.4426950408889634f;

    auto issueKV = [&](int st, int kt) {
        const float* Kt = Kb + (size_t)kt * 64 * DDIM;
        const float* Vt = Vb + (size_t)kt * 64 * DDIM;
#pragma unroll
        for (int t = 0; t < 8; t++) {
            int i = tid + t * 128;
            int r = i >> 4;
            int c4 = (i & 15) << 2;
            uint32_t off = (uint32_t)((st * 64 + r) * AP + c4) * 4;
            cp16(sK + off, Kt + (size_t)r * DDIM + c4);
            cp16(sV + off, Vt + (size_t)r * DDIM + c4);
        }
        if (tid < 64) cp4(sM + (uint32_t)(st * 64 + tid) * 4, &mask[(size_t)b * SS + kt * 64 + tid]);
    };

    const int ktmax = 2 * qi + 1;
    issueKV(0, 0);
    cp_commit();

    // stage Q (128x64) through Ps, then pull fragments into registers
#pragma unroll
    for (int t = 0; t < 16; t++) {
        int i = tid + t * 128;
        int r = i >> 4;
        int c4 = (i & 15) << 2;
        float4 v = *reinterpret_cast<const float4*>(Qb + (size_t)r * DDIM + c4);
        uint32_t* p = &Ps[r * AP + c4];
        p[0] = f2tf32(v.x * qscale); p[1] = f2tf32(v.y * qscale);
        p[2] = f2tf32(v.z * qscale); p[3] = f2tf32(v.w * qscale);
    }
    __syncthreads();

    uint32_t qf[2][8][4];
#pragma unroll
    for (int mt = 0; mt < 2; mt++) {
        int r = wrow + mt * 16;
#pragma unroll
        for (int ks = 0; ks < 8; ks++) {
            int kk = ks * 8;
            qf[mt][ks][0] = Ps[(r + g) * AP + kk + tig];
            qf[mt][ks][1] = Ps[(r + g + 8) * AP + kk + tig];
            qf[mt][ks][2] = Ps[(r + g) * AP + kk + tig + 4];
            qf[mt][ks][3] = Ps[(r + g + 8) * AP + kk + tig + 4];
        }
    }

    float mrow[2][2], lrow[2][2];
    float o[2][8][4];
#pragma unroll
    for (int mt = 0; mt < 2; mt++) {
        mrow[mt][0] = mrow[mt][1] = -1e30f;
        lrow[mt][0] = lrow[mt][1] = 0.f;
#pragma unroll
        for (int nt = 0; nt < 8; nt++)
#pragma unroll
            for (int e = 0; e < 4; e++) o[mt][nt][e] = 0.f;
    }

    const int rowmax = qi * AQT + wrow + 31;

    for (int kt = 0; kt <= ktmax; kt++) {
        const int cur = kt & 1;
        __syncthreads();                 // stage cur^1 free (everyone done with kt-1)
        if (kt < ktmax) {
            issueKV(cur ^ 1, kt + 1);
            cp_commit();
            cp_wait<1>();
        } else {
            cp_wait<0>();
        }
        __syncthreads();                 // stage cur visible to all

        const float* Ksr = Ks0 + cur * 64 * AP;
        const float* Vsr = Vs0 + cur * 64 * AP;
        const int* msk = msk0 + cur * 64;

        if (kt * 64 > rowmax) continue;  // warp-uniform skip of fully-masked tiles

        // S = Q @ K^T : 32x64 per warp (2 m-tiles), cvt at load
        float s[2][8][4];
#pragma unroll
        for (int mt = 0; mt < 2; mt++)
#pragma unroll
            for (int nt = 0; nt < 8; nt++)
                s[mt][nt][0] = s[mt][nt][1] = s[mt][nt][2] = s[mt][nt][3] = 0.f;

#pragma unroll
        for (int ks = 0; ks < 8; ks++) {
            int kk = ks * 8;
            uint32_t bf[8][2];
#pragma unroll
            for (int nt = 0; nt < 8; nt++) {
                bf[nt][0] = f2tf32(Ksr[(nt * 8 + g) * AP + kk + tig]);
                bf[nt][1] = f2tf32(Ksr[(nt * 8 + g) * AP + kk + tig + 4]);
            }
#pragma unroll
            for (int mt = 0; mt < 2; mt++)
#pragma unroll
                for (int nt = 0; nt < 8; nt++)
                    mma_tf32(s[mt][nt], qf[mt][ks][0], qf[mt][ks][1],
                             qf[mt][ks][2], qf[mt][ks][3], bf[nt][0], bf[nt][1]);
        }

        // masking + online softmax per m-tile
#pragma unroll
        for (int mt = 0; mt < 2; mt++) {
            const int q0 = qi * AQT + wrow + mt * 16 + g;
            const int q1 = q0 + 8;
            const bool needc = (kt * 64 + 63 > qi * AQT + wrow + mt * 16);
#pragma unroll
            for (int nt = 0; nt < 8; nt++) {
                int cl = nt * 8 + 2 * tig;
                int cg = kt * 64 + cl;
                bool mv0 = (msk[cl] != 0);
                bool mv1 = (msk[cl + 1] != 0);
                if (!mv0 || (needc && cg > q0))     s[mt][nt][0] = -1e30f;
                if (!mv1 || (needc && cg + 1 > q0)) s[mt][nt][1] = -1e30f;
                if (!mv0 || (needc && cg > q1))     s[mt][nt][2] = -1e30f;
                if (!mv1 || (needc && cg + 1 > q1)) s[mt][nt][3] = -1e30f;
            }

            float rm0 = -1e30f, rm1 = -1e30f;
#pragma unroll
            for (int nt = 0; nt < 8; nt++) {
                rm0 = fmaxf(rm0, fmaxf(s[mt][nt][0], s[mt][nt][1]));
                rm1 = fmaxf(rm1, fmaxf(s[mt][nt][2], s[mt][nt][3]));
            }
            rm0 = fmaxf(rm0, __shfl_xor_sync(0xffffffffu, rm0, 1));
            rm0 = fmaxf(rm0, __shfl_xor_sync(0xffffffffu, rm0, 2));
            rm1 = fmaxf(rm1, __shfl_xor_sync(0xffffffffu, rm1, 1));
            rm1 = fmaxf(rm1, __shfl_xor_sync(0xffffffffu, rm1, 2));

            float mn0 = fmaxf(mrow[mt][0], rm0);
            float mn1 = fmaxf(mrow[mt][1], rm1);
            float al0 = ex2(mrow[mt][0] - mn0);
            float al1 = ex2(mrow[mt][1] - mn1);
            mrow[mt][0] = mn0; mrow[mt][1] = mn1;

            float rs0 = 0.f, rs1 = 0.f;
            const int pr = wrow + mt * 16;
#pragma unroll
            for (int nt = 0; nt < 8; nt++) {
                int cl = nt * 8 + 2 * tig;
                float p0 = ex2(s[mt][nt][0] - mn0);
                float p1 = ex2(s[mt][nt][1] - mn0);
                float p2 = ex2(s[mt][nt][2] - mn1);
                float p3 = ex2(s[mt][nt][3] - mn1);
                rs0 += p0 + p1;
                rs1 += p2 + p3;
                Ps[(pr + g) * AP + cl]         = f2tf32(p0);
                Ps[(pr + g) * AP + cl + 1]     = f2tf32(p1);
                Ps[(pr + g + 8) * AP + cl]     = f2tf32(p2);
                Ps[(pr + g + 8) * AP + cl + 1] = f2tf32(p3);
            }
            rs0 += __shfl_xor_sync(0xffffffffu, rs0, 1);
            rs0 += __shfl_xor_sync(0xffffffffu, rs0, 2);
            rs1 += __shfl_xor_sync(0xffffffffu, rs1, 1);
            rs1 += __shfl_xor_sync(0xffffffffu, rs1, 2);
            lrow[mt][0] = lrow[mt][0] * al0 + rs0;
            lrow[mt][1] = lrow[mt][1] * al1 + rs1;

#pragma unroll
            for (int nt = 0; nt < 8; nt++) {
                o[mt][nt][0] *= al0; o[mt][nt][1] *= al0;
                o[mt][nt][2] *= al1; o[mt][nt][3] *= al1;
            }
        }
        __syncwarp();

        // O += P @ V (cvt V at load)
#pragma unroll
        for (int ks = 0; ks < 8; ks++) {
            int kk = ks * 8;
            uint32_t vb[8][2];
#pragma unroll
            for (int nt = 0; nt < 8; nt++) {
                vb[nt][0] = f2tf32(Vsr[(kk + tig) * AP + nt * 8 + g]);
                vb[nt][1] = f2tf32(Vsr[(kk + tig + 4) * AP + nt * 8 + g]);
            }
#pragma unroll
            for (int mt = 0; mt < 2; mt++) {
                const int pr = wrow + mt * 16;
                uint32_t a0 = Ps[(pr + g) * AP + kk + tig];
                uint32_t a1 = Ps[(pr + g + 8) * AP + kk + tig];
                uint32_t a2 = Ps[(pr + g) * AP + kk + tig + 4];
                uint32_t a3 = Ps[(pr + g + 8) * AP + kk + tig + 4];
#pragma unroll
                for (int nt = 0; nt < 8; nt++)
                    mma_tf32(o[mt][nt], a0, a1, a2, a3, vb[nt][0], vb[nt][1]);
            }
        }
    }

    // normalize + store
#pragma unroll
    for (int mt = 0; mt < 2; mt++) {
        float i0 = 1.f / lrow[mt][0];
        float i1 = 1.f / lrow[mt][1];
        int r0 = wrow + mt * 16 + g;
#pragma unroll
        for (int nt = 0; nt < 8; nt++) {
            int cl = nt * 8 + 2 * tig;
            *reinterpret_cast<float2*>(&Ob[(size_t)r0 * DDIM + cl]) =
                make_float2(o[mt][nt][0] * i0, o[mt][nt][1] * i0);
            *reinterpret_cast<float2*>(&Ob[(size_t)(r0 + 8) * DDIM + cl]) =
                make_float2(o[mt][nt][2] * i1, o[mt][nt][3] * i1);
        }
    }
}

// ---------------- launch ----------------
extern "C" void kernel_launch(void* const* d_in, const int* in_sizes, int n_in,
                              void* d_out, int out_size) {
    const float* xq = (const float*)d_in[0];
    const float* xk = (const float*)d_in[1];
    const float* xv = (const float*)d_in[2];
    const int* mask = (const int*)d_in[3];
    const float* Wq = (const float*)d_in[4];
    const float* Wk = (const float*)d_in[5];
    const float* Wv = (const float*)d_in[6];
    const float* Wo = (const float*)d_in[7];
    float* out = (float*)d_out;

    float *Qp, *Kp, *Vp, *Ap;
    cudaGetSymbolAddress((void**)&Qp, g_Q);
    cudaGetSymbolAddress((void**)&Kp, g_K);
    cudaGetSymbolAddress((void**)&Vp, g_V);
    cudaGetSymbolAddress((void**)&Ap, g_A);

    cudaFuncSetAttribute(gemm_nt, cudaFuncAttributeMaxDynamicSharedMemorySize, GSMEM);
    cudaFuncSetAttribute(attn_kernel, cudaFuncAttributeMaxDynamicSharedMemorySize, ASMEM);

    // fused QKV projections (gridDim.z selects the GEMM)
    gemm_nt<<<dim3(DDIM / GBN, MTOT / GBM, 3), 256, GSMEM>>>(
        xq, xk, xv, Wq, Wk, Wv, Qp, Kp, Vp);

    attn_kernel<<<dim3(SS / AQT, BB * HH), 128, ASMEM>>>(Qp, Kp, Vp, mask, Ap);

    gemm_nt<<<dim3(DDIM / GBN, MTOT / GBM, 1), 256, GSMEM>>>(
        Ap, Ap, Ap, Wo, Wo, Wo, out, out, out);
}

// round 6
// speedup vs baseline: 1.0783x; 1.0376x over previous
#include <cuda_runtime.h>
#include <cstdint>

#define BB 4
#define SS 2048
#define DDIM 1024
#define HH 16
#define DKK 64
#define MTOT (BB*SS)   // 8192

// ---------------- scratch (static __device__, allocation-free) ----------------
__device__ float g_Q[(size_t)MTOT*DDIM];
__device__ float g_K[(size_t)MTOT*DDIM];
__device__ float g_V[(size_t)MTOT*DDIM];
__device__ float g_A[(size_t)MTOT*DDIM];
__device__ float g_Xq[(size_t)MTOT*DDIM];
__device__ float g_Xk[(size_t)MTOT*DDIM];
__device__ float g_Xv[(size_t)MTOT*DDIM];
__device__ float g_W[4][(size_t)DDIM*DDIM];

// ---------------- helpers ----------------
__device__ __forceinline__ uint32_t f2tf32(float f) {
    uint32_t u;
    asm("cvt.rna.tf32.f32 %0, %1;" : "=r"(u) : "f"(f));
    return u;
}
__device__ __forceinline__ float ex2(float x) {
    float y;
    asm("ex2.approx.ftz.f32 %0, %1;" : "=f"(y) : "f"(x));
    return y;
}
__device__ __forceinline__ void cp16(uint32_t saddr, const void* g) {
    asm volatile("cp.async.cg.shared.global [%0], [%1], 16;" :: "r"(saddr), "l"(g));
}
__device__ __forceinline__ void cp4(uint32_t saddr, const void* g) {
    asm volatile("cp.async.ca.shared.global [%0], [%1], 4;" :: "r"(saddr), "l"(g));
}
__device__ __forceinline__ void cp_commit() {
    asm volatile("cp.async.commit_group;");
}
template <int N>
__device__ __forceinline__ void cp_wait() {
    asm volatile("cp.async.wait_group %0;" :: "n"(N));
}
// 8x8 tf32 tile == one b16 ldmatrix unit (8 rows x 16B); thread t gets (row t/4, col t%4)
__device__ __forceinline__ void ldsm4(uint32_t& r0, uint32_t& r1, uint32_t& r2, uint32_t& r3,
                                      uint32_t addr) {
    asm volatile("ldmatrix.sync.aligned.m8n8.x4.shared.b16 {%0,%1,%2,%3}, [%4];"
                 : "=r"(r0), "=r"(r1), "=r"(r2), "=r"(r3) : "r"(addr));
}

// D(16x8,f32) += A(16x8,tf32,row) * B(8x8,tf32,col)
__device__ __forceinline__ void mma_tf32(float c[4],
                                         uint32_t a0, uint32_t a1, uint32_t a2, uint32_t a3,
                                         uint32_t b0, uint32_t b1) {
    asm volatile(
        "mma.sync.aligned.m16n8k8.row.col.f32.tf32.tf32.f32 "
        "{%0,%1,%2,%3}, {%4,%5,%6,%7}, {%8,%9}, {%0,%1,%2,%3};"
        : "+f"(c[0]), "+f"(c[1]), "+f"(c[2]), "+f"(c[3])
        : "r"(a0), "r"(a1), "r"(a2), "r"(a3), "r"(b0), "r"(b1));
}

// ---------------- pre-round to tf32-representable fp32 ----------------
__global__ void round_tf32_k(const float4* __restrict__ in, float4* __restrict__ out, int n4) {
    int i = blockIdx.x * blockDim.x + threadIdx.x;
    int stride = gridDim.x * blockDim.x;
    for (; i < n4; i += stride) {
        float4 v = in[i];
        v.x = __uint_as_float(f2tf32(v.x));
        v.y = __uint_as_float(f2tf32(v.y));
        v.z = __uint_as_float(f2tf32(v.z));
        v.w = __uint_as_float(f2tf32(v.w));
        out[i] = v;
    }
}

// ---------------- GEMM: C[m][n] = sum_k A[m][k] * W[n][k] ----------------
// block 128x128, warp 64x32, 3-stage cp.async, ldmatrix fragments, no inner cvt
#define GBM 128
#define GBN 128
#define GBK 32
#define GST (GBK + 4)                         // 36-float row stride (36 mod 32 = 4 -> LDSM conflict-free)
#define GSTG (GBM * GST)
#define GNS 3
#define GSMEM (2 * GNS * GSTG * 4)            // 110592 B

__global__ __launch_bounds__(256, 1)
void gemm_nt(const float* __restrict__ A0, const float* __restrict__ A1, const float* __restrict__ A2,
             const float* __restrict__ W0, const float* __restrict__ W1, const float* __restrict__ W2,
             float* __restrict__ C0, float* __restrict__ C1, float* __restrict__ C2,
             int roundOut) {
    extern __shared__ float gsm[];
    float* Asm = gsm;
    float* Bsm = gsm + GNS * GSTG;

    const int z = blockIdx.z;
    const float* A = (z == 0) ? A0 : (z == 1) ? A1 : A2;
    const float* W = (z == 0) ? W0 : (z == 1) ? W1 : W2;
    float*       C = (z == 0) ? C0 : (z == 1) ? C1 : C2;

    const int m0 = blockIdx.y * GBM;
    const int n0 = blockIdx.x * GBN;
    const int tid = threadIdx.x;
    const int w = tid >> 5, lane = tid & 31;
    const int g = lane >> 2, tig = lane & 3;
    const int wm = (w >> 2) * 64;
    const int wn = (w & 3) * 32;

    const int lr = tid >> 3;
    const int lc = (tid & 7) << 2;

    const uint32_t sA = (uint32_t)__cvta_generic_to_shared(Asm);
    const uint32_t sB = (uint32_t)__cvta_generic_to_shared(Bsm);

    // ldmatrix per-thread address components
    const int lane7 = lane & 7;
    // A frags: mat = lane>>3 : {(m,k0),(m+8,k0),(m,k4),(m+8,k4)}
    const int a_ro = ((lane >> 3) & 1) * 8;
    const int a_ko = ((lane >> 4) & 1) * 4;
    // B frags: mat = lane>>3 : {(n0t,k0),(n0t,k4),(n1t,k0),(n1t,k4)}
    const int b_no = ((lane >> 4) & 1) * 8;
    const int b_ko = ((lane >> 3) & 1) * 4;

    uint32_t aIdx[4];
#pragma unroll
    for (int mt = 0; mt < 4; mt++)
        aIdx[mt] = (uint32_t)(((wm + mt * 16 + a_ro + lane7) * GST + a_ko) * 4);
    const uint32_t bIdx = (uint32_t)(((wn + b_no + lane7) * GST + b_ko) * 4);

    float acc[4][4][4];
#pragma unroll
    for (int i = 0; i < 4; i++)
#pragma unroll
        for (int j = 0; j < 4; j++)
#pragma unroll
            for (int e = 0; e < 4; e++) acc[i][j][e] = 0.f;

    auto issue = [&](int st, int k0) {
#pragma unroll
        for (int it = 0; it < 4; it++) {
            int row = lr + it * 32;
            cp16(sA + (uint32_t)((st * GBM + row) * GST + lc) * 4,
                 &A[(size_t)(m0 + row) * DDIM + k0 + lc]);
            cp16(sB + (uint32_t)((st * GBN + row) * GST + lc) * 4,
                 &W[(size_t)(n0 + row) * DDIM + k0 + lc]);
        }
    };

    issue(0, 0); cp_commit();
    issue(1, GBK); cp_commit();

    const int NKT = DDIM / GBK;       // 32
    for (int kt = 0; kt < NKT; kt++) {
        if (kt < NKT - 1) cp_wait<1>(); else cp_wait<0>();
        __syncthreads();

        const int st = kt % GNS;
        const uint32_t stb = (uint32_t)(st * GSTG * 4);

#pragma unroll
        for (int ks = 0; ks < 4; ks++) {
            const uint32_t ksB = (uint32_t)(ks * 32);   // 8 floats = 32 bytes
            uint32_t b[4][2];
            uint32_t bb = sB + stb + bIdx + ksB;
            ldsm4(b[0][0], b[0][1], b[1][0], b[1][1], bb);
            ldsm4(b[2][0], b[2][1], b[3][0], b[3][1], bb + 16 * GST * 4);
#pragma unroll
            for (int mt = 0; mt < 4; mt++) {
                uint32_t a0, a1, a2, a3;
                ldsm4(a0, a1, a2, a3, sA + stb + aIdx[mt] + ksB);
#pragma unroll
                for (int nt = 0; nt < 4; nt++)
                    mma_tf32(acc[mt][nt], a0, a1, a2, a3, b[nt][0], b[nt][1]);
            }
        }

        if (kt + 2 < NKT) {
            issue((kt + 2) % GNS, (kt + 2) * GBK);
            cp_commit();
        }
    }

#pragma unroll
    for (int mt = 0; mt < 4; mt++) {
        int r0 = m0 + wm + mt * 16 + g;
#pragma unroll
        for (int nt = 0; nt < 4; nt++) {
            int col = n0 + wn + nt * 8 + 2 * tig;
            float v0 = acc[mt][nt][0], v1 = acc[mt][nt][1];
            float v2 = acc[mt][nt][2], v3 = acc[mt][nt][3];
            if (roundOut) {
                v0 = __uint_as_float(f2tf32(v0)); v1 = __uint_as_float(f2tf32(v1));
                v2 = __uint_as_float(f2tf32(v2)); v3 = __uint_as_float(f2tf32(v3));
            }
            *reinterpret_cast<float2*>(&C[(size_t)r0 * DDIM + col]) = make_float2(v0, v1);
            *reinterpret_cast<float2*>(&C[(size_t)(r0 + 8) * DDIM + col]) = make_float2(v2, v3);
        }
    }
}

// ---------------- flash attention: pre-rounded K/V, ldmatrix frags, double-buffer ----------------
#define AQT 128
#define AP 68    // 68 mod 32 = 4 -> LDSM conflict-free
#define ASMEM ((2*64 + 2*64 + 128) * AP * 4 + 2 * 64 * 4)

__global__ __launch_bounds__(128, 1)
void attn_kernel(const float* __restrict__ Q, const float* __restrict__ K,
                 const float* __restrict__ V, const int* __restrict__ mask,
                 float* __restrict__ O) {
    extern __shared__ uint32_t smem_u[];
    uint32_t* Ks0 = smem_u;                      // 2 stages x 64 rows (tf32 bits)
    uint32_t* Vs0 = Ks0 + 2 * 64 * AP;
    uint32_t* Ps  = Vs0 + 2 * 64 * AP;           // 128 rows (Q staging + P)
    int* msk0 = (int*)(Ps + 128 * AP);

    const int qi = gridDim.x - 1 - blockIdx.x;   // heavy tiles first
    const int bh = blockIdx.y;
    const int b = bh / HH, h = bh % HH;

    const int tid = threadIdx.x;
    const int w = tid >> 5, lane = tid & 31;
    const int g = lane >> 2, tig = lane & 3;
    const int wrow = w * 32;

    const float* Qb = Q + ((size_t)b * SS + (size_t)qi * AQT) * DDIM + h * DKK;
    const float* Kb = K + (size_t)b * SS * DDIM + h * DKK;
    const float* Vb = V + (size_t)b * SS * DDIM + h * DKK;
    float* Ob = O + ((size_t)b * SS + (size_t)qi * AQT) * DDIM + h * DKK;

    const uint32_t sK = (uint32_t)__cvta_generic_to_shared(Ks0);
    const uint32_t sV = (uint32_t)__cvta_generic_to_shared(Vs0);
    const uint32_t sP = (uint32_t)__cvta_generic_to_shared(Ps);
    const uint32_t sM = (uint32_t)__cvta_generic_to_shared(msk0);

    // ldmatrix address components
    const int lane7 = lane & 7;
    const int a_ro = ((lane >> 3) & 1) * 8;
    const int a_ko = ((lane >> 4) & 1) * 4;
    const int b_no = ((lane >> 4) & 1) * 8;
    const int b_ko = ((lane >> 3) & 1) * 4;

    const float qscale = 0.125f * 1.4426950408889634f;

    auto issueKV = [&](int st, int kt) {
        const float* Kt = Kb + (size_t)kt * 64 * DDIM;
        const float* Vt = Vb + (size_t)kt * 64 * DDIM;
#pragma unroll
        for (int t = 0; t < 8; t++) {
            int i = tid + t * 128;
            int r = i >> 4;
            int c4 = (i & 15) << 2;
            uint32_t off = (uint32_t)((st * 64 + r) * AP + c4) * 4;
            cp16(sK + off, Kt + (size_t)r * DDIM + c4);
            cp16(sV + off, Vt + (size_t)r * DDIM + c4);
        }
        if (tid < 64) cp4(sM + (uint32_t)(st * 64 + tid) * 4, &mask[(size_t)b * SS + kt * 64 + tid]);
    };

    const int ktmax = 2 * qi + 1;
    issueKV(0, 0);
    cp_commit();

    // stage Q (128x64), scale+round, then pull fragments via ldmatrix
#pragma unroll
    for (int t = 0; t < 16; t++) {
        int i = tid + t * 128;
        int r = i >> 4;
        int c4 = (i & 15) << 2;
        float4 v = *reinterpret_cast<const float4*>(Qb + (size_t)r * DDIM + c4);
        uint32_t* p = &Ps[r * AP + c4];
        p[0] = f2tf32(v.x * qscale); p[1] = f2tf32(v.y * qscale);
        p[2] = f2tf32(v.z * qscale); p[3] = f2tf32(v.w * qscale);
    }
    __syncthreads();

    uint32_t qf[2][8][4];
#pragma unroll
    for (int mt = 0; mt < 2; mt++) {
        const uint32_t base = sP + (uint32_t)(((wrow + mt * 16 + a_ro + lane7) * AP + a_ko) * 4);
#pragma unroll
        for (int ks = 0; ks < 8; ks++)
            ldsm4(qf[mt][ks][0], qf[mt][ks][1], qf[mt][ks][2], qf[mt][ks][3],
                  base + (uint32_t)(ks * 32));
    }

    float mrow[2][2], lrow[2][2];
    float o[2][8][4];
#pragma unroll
    for (int mt = 0; mt < 2; mt++) {
        mrow[mt][0] = mrow[mt][1] = -1e30f;
        lrow[mt][0] = lrow[mt][1] = 0.f;
#pragma unroll
        for (int nt = 0; nt < 8; nt++)
#pragma unroll
            for (int e = 0; e < 4; e++) o[mt][nt][e] = 0.f;
    }

    const int rowmax = qi * AQT + wrow + 31;

    for (int kt = 0; kt <= ktmax; kt++) {
        const int cur = kt & 1;
        __syncthreads();
        if (kt < ktmax) {
            issueKV(cur ^ 1, kt + 1);
            cp_commit();
            cp_wait<1>();
        } else {
            cp_wait<0>();
        }
        __syncthreads();

        const uint32_t sKst = sK + (uint32_t)(cur * 64 * AP * 4);
        const uint32_t* Vsr = Vs0 + cur * 64 * AP;
        const int* msk = msk0 + cur * 64;

        if (kt * 64 > rowmax) continue;

        // S = Q @ K^T : 32x64 per warp, K frags via ldmatrix (raw pre-rounded bits)
        float s[2][8][4];
#pragma unroll
        for (int mt = 0; mt < 2; mt++)
#pragma unroll
            for (int nt = 0; nt < 8; nt++)
                s[mt][nt][0] = s[mt][nt][1] = s[mt][nt][2] = s[mt][nt][3] = 0.f;

        const uint32_t kb0 = sKst + (uint32_t)(((b_no + lane7) * AP + b_ko) * 4);
#pragma unroll
        for (int ks = 0; ks < 8; ks++) {
            const uint32_t ksB = (uint32_t)(ks * 32);
            uint32_t bf[8][2];
#pragma unroll
            for (int j = 0; j < 4; j++)
                ldsm4(bf[2*j][0], bf[2*j][1], bf[2*j+1][0], bf[2*j+1][1],
                      kb0 + (uint32_t)(j * 16 * AP * 4) + ksB);
#pragma unroll
            for (int mt = 0; mt < 2; mt++)
#pragma unroll
                for (int nt = 0; nt < 8; nt++)
                    mma_tf32(s[mt][nt], qf[mt][ks][0], qf[mt][ks][1],
                             qf[mt][ks][2], qf[mt][ks][3], bf[nt][0], bf[nt][1]);
        }

        // masking + online softmax
#pragma unroll
        for (int mt = 0; mt < 2; mt++) {
            const int q0 = qi * AQT + wrow + mt * 16 + g;
            const int q1 = q0 + 8;
            const bool needc = (kt * 64 + 63 > qi * AQT + wrow + mt * 16);
#pragma unroll
            for (int nt = 0; nt < 8; nt++) {
                int cl = nt * 8 + 2 * tig;
                int cg = kt * 64 + cl;
                bool mv0 = (msk[cl] != 0);
                bool mv1 = (msk[cl + 1] != 0);
                if (!mv0 || (needc && cg > q0))     s[mt][nt][0] = -1e30f;
                if (!mv1 || (needc && cg + 1 > q0)) s[mt][nt][1] = -1e30f;
                if (!mv0 || (needc && cg > q1))     s[mt][nt][2] = -1e30f;
                if (!mv1 || (needc && cg + 1 > q1)) s[mt][nt][3] = -1e30f;
            }

            float rm0 = -1e30f, rm1 = -1e30f;
#pragma unroll
            for (int nt = 0; nt < 8; nt++) {
                rm0 = fmaxf(rm0, fmaxf(s[mt][nt][0], s[mt][nt][1]));
                rm1 = fmaxf(rm1, fmaxf(s[mt][nt][2], s[mt][nt][3]));
            }
            rm0 = fmaxf(rm0, __shfl_xor_sync(0xffffffffu, rm0, 1));
            rm0 = fmaxf(rm0, __shfl_xor_sync(0xffffffffu, rm0, 2));
            rm1 = fmaxf(rm1, __shfl_xor_sync(0xffffffffu, rm1, 1));
            rm1 = fmaxf(rm1, __shfl_xor_sync(0xffffffffu, rm1, 2));

            float mn0 = fmaxf(mrow[mt][0], rm0);
            float mn1 = fmaxf(mrow[mt][1], rm1);
            float al0 = ex2(mrow[mt][0] - mn0);
            float al1 = ex2(mrow[mt][1] - mn1);
            mrow[mt][0] = mn0; mrow[mt][1] = mn1;

            float rs0 = 0.f, rs1 = 0.f;
            const int pr = wrow + mt * 16;
#pragma unroll
            for (int nt = 0; nt < 8; nt++) {
                int cl = nt * 8 + 2 * tig;
                float p0 = ex2(s[mt][nt][0] - mn0);
                float p1 = ex2(s[mt][nt][1] - mn0);
                float p2 = ex2(s[mt][nt][2] - mn1);
                float p3 = ex2(s[mt][nt][3] - mn1);
                rs0 += p0 + p1;
                rs1 += p2 + p3;
                Ps[(pr + g) * AP + cl]         = f2tf32(p0);
                Ps[(pr + g) * AP + cl + 1]     = f2tf32(p1);
                Ps[(pr + g + 8) * AP + cl]     = f2tf32(p2);
                Ps[(pr + g + 8) * AP + cl + 1] = f2tf32(p3);
            }
            rs0 += __shfl_xor_sync(0xffffffffu, rs0, 1);
            rs0 += __shfl_xor_sync(0xffffffffu, rs0, 2);
            rs1 += __shfl_xor_sync(0xffffffffu, rs1, 1);
            rs1 += __shfl_xor_sync(0xffffffffu, rs1, 2);
            lrow[mt][0] = lrow[mt][0] * al0 + rs0;
            lrow[mt][1] = lrow[mt][1] * al1 + rs1;

#pragma unroll
            for (int nt = 0; nt < 8; nt++) {
                o[mt][nt][0] *= al0; o[mt][nt][1] *= al0;
                o[mt][nt][2] *= al1; o[mt][nt][3] *= al1;
            }
        }
        __syncwarp();

        // O += P @ V : P frags via ldmatrix, V raw (pre-rounded bits)
#pragma unroll
        for (int ks = 0; ks < 8; ks++) {
            int kk = ks * 8;
            uint32_t vb[8][2];
#pragma unroll
            for (int nt = 0; nt < 8; nt++) {
                vb[nt][0] = Vsr[(kk + tig) * AP + nt * 8 + g];
                vb[nt][1] = Vsr[(kk + tig + 4) * AP + nt * 8 + g];
            }
#pragma unroll
            for (int mt = 0; mt < 2; mt++) {
                const int pr = wrow + mt * 16;
                uint32_t a0, a1, a2, a3;
                ldsm4(a0, a1, a2, a3,
                      sP + (uint32_t)(((pr + a_ro + lane7) * AP + kk + a_ko) * 4));
#pragma unroll
                for (int nt = 0; nt < 8; nt++)
                    mma_tf32(o[mt][nt], a0, a1, a2, a3, vb[nt][0], vb[nt][1]);
            }
        }
    }

    // normalize + store (rounded: feeds the Wo tf32 GEMM)
#pragma unroll
    for (int mt = 0; mt < 2; mt++) {
        float i0 = 1.f / lrow[mt][0];
        float i1 = 1.f / lrow[mt][1];
        int r0 = wrow + mt * 16 + g;
#pragma unroll
        for (int nt = 0; nt < 8; nt++) {
            int cl = nt * 8 + 2 * tig;
            *reinterpret_cast<float2*>(&Ob[(size_t)r0 * DDIM + cl]) =
                make_float2(__uint_as_float(f2tf32(o[mt][nt][0] * i0)),
                            __uint_as_float(f2tf32(o[mt][nt][1] * i0)));
            *reinterpret_cast<float2*>(&Ob[(size_t)(r0 + 8) * DDIM + cl]) =
                make_float2(__uint_as_float(f2tf32(o[mt][nt][2] * i1)),
                            __uint_as_float(f2tf32(o[mt][nt][3] * i1)));
        }
    }
}

// ---------------- launch ----------------
extern "C" void kernel_launch(void* const* d_in, const int* in_sizes, int n_in,
                              void* d_out, int out_size) {
    const float* xq = (const float*)d_in[0];
    const float* xk = (const float*)d_in[1];
    const float* xv = (const float*)d_in[2];
    const int* mask = (const int*)d_in[3];
    const float* Wq = (const float*)d_in[4];
    const float* Wk = (const float*)d_in[5];
    const float* Wv = (const float*)d_in[6];
    const float* Wo = (const float*)d_in[7];
    float* out = (float*)d_out;

    float *Qp, *Kp, *Vp, *Ap, *Xq, *Xk, *Xv, *Wr;
    cudaGetSymbolAddress((void**)&Qp, g_Q);
    cudaGetSymbolAddress((void**)&Kp, g_K);
    cudaGetSymbolAddress((void**)&Vp, g_V);
    cudaGetSymbolAddress((void**)&Ap, g_A);
    cudaGetSymbolAddress((void**)&Xq, g_Xq);
    cudaGetSymbolAddress((void**)&Xk, g_Xk);
    cudaGetSymbolAddress((void**)&Xv, g_Xv);
    cudaGetSymbolAddress((void**)&Wr, g_W);

    float* Wr0 = Wr;
    float* Wr1 = Wr + (size_t)DDIM * DDIM;
    float* Wr2 = Wr + 2 * (size_t)DDIM * DDIM;
    float* Wr3 = Wr + 3 * (size_t)DDIM * DDIM;

    cudaFuncSetAttribute(gemm_nt, cudaFuncAttributeMaxDynamicSharedMemorySize, GSMEM);
    cudaFuncSetAttribute(attn_kernel, cudaFuncAttributeMaxDynamicSharedMemorySize, ASMEM);

    const int NX4 = (MTOT * DDIM) / 4;
    const int NW4 = (DDIM * DDIM) / 4;
    round_tf32_k<<<2048, 256>>>((const float4*)xq, (float4*)Xq, NX4);
    round_tf32_k<<<2048, 256>>>((const float4*)xk, (float4*)Xk, NX4);
    round_tf32_k<<<2048, 256>>>((const float4*)xv, (float4*)Xv, NX4);
    round_tf32_k<<<512, 256>>>((const float4*)Wq, (float4*)Wr0, NW4);
    round_tf32_k<<<512, 256>>>((const float4*)Wk, (float4*)Wr1, NW4);
    round_tf32_k<<<512, 256>>>((const float4*)Wv, (float4*)Wr2, NW4);
    round_tf32_k<<<512, 256>>>((const float4*)Wo, (float4*)Wr3, NW4);

    // fused QKV projections; outputs rounded to tf32 for attention consumption
    gemm_nt<<<dim3(DDIM / GBN, MTOT / GBM, 3), 256, GSMEM>>>(
        Xq, Xk, Xv, Wr0, Wr1, Wr2, Qp, Kp, Vp, 1);

    attn_kernel<<<dim3(SS / AQT, BB * HH), 128, ASMEM>>>(Qp, Kp, Vp, mask, Ap);

    // output projection; exact fp32 output
    gemm_nt<<<dim3(DDIM / GBN, MTOT / GBM, 1), 256, GSMEM>>>(
        Ap, Ap, Ap, Wr3, Wr3, Wr3, out, out, out, 0);
}

// round 7
// speedup vs baseline: 1.1639x; 1.0793x over previous
#include <cuda_runtime.h>
#include <cstdint>

#define BB 4
#define SS 2048
#define DDIM 1024
#define HH 16
#define DKK 64
#define MTOT (BB*SS)   // 8192

// ---------------- scratch (static __device__, allocation-free) ----------------
__device__ float g_Q[(size_t)MTOT*DDIM];
__device__ float g_K[(size_t)MTOT*DDIM];
__device__ float g_V[(size_t)MTOT*DDIM];
__device__ float g_A[(size_t)MTOT*DDIM];

// ---------------- helpers ----------------
__device__ __forceinline__ uint32_t f2tf32(float f) {
    uint32_t u;
    asm("cvt.rna.tf32.f32 %0, %1;" : "=r"(u) : "f"(f));
    return u;
}
__device__ __forceinline__ uint32_t bits2tf32(uint32_t b) {
    return f2tf32(__uint_as_float(b));
}
__device__ __forceinline__ float ex2(float x) {
    float y;
    asm("ex2.approx.ftz.f32 %0, %1;" : "=f"(y) : "f"(x));
    return y;
}
__device__ __forceinline__ void cp16(uint32_t saddr, const void* g) {
    asm volatile("cp.async.cg.shared.global [%0], [%1], 16;" :: "r"(saddr), "l"(g));
}
__device__ __forceinline__ void cp4(uint32_t saddr, const void* g) {
    asm volatile("cp.async.ca.shared.global [%0], [%1], 4;" :: "r"(saddr), "l"(g));
}
__device__ __forceinline__ void cp_commit() {
    asm volatile("cp.async.commit_group;");
}
template <int N>
__device__ __forceinline__ void cp_wait() {
    asm volatile("cp.async.wait_group %0;" :: "n"(N));
}
// 8x8 tf32 tile == one b16 ldmatrix unit (8 rows x 16B); thread t gets (row t/4, col t%4)
__device__ __forceinline__ void ldsm4(uint32_t& r0, uint32_t& r1, uint32_t& r2, uint32_t& r3,
                                      uint32_t addr) {
    asm volatile("ldmatrix.sync.aligned.m8n8.x4.shared.b16 {%0,%1,%2,%3}, [%4];"
                 : "=r"(r0), "=r"(r1), "=r"(r2), "=r"(r3) : "r"(addr));
}

// D(16x8,f32) += A(16x8,tf32,row) * B(8x8,tf32,col)
__device__ __forceinline__ void mma_tf32(float c[4],
                                         uint32_t a0, uint32_t a1, uint32_t a2, uint32_t a3,
                                         uint32_t b0, uint32_t b1) {
    asm volatile(
        "mma.sync.aligned.m16n8k8.row.col.f32.tf32.tf32.f32 "
        "{%0,%1,%2,%3}, {%4,%5,%6,%7}, {%8,%9}, {%0,%1,%2,%3};"
        : "+f"(c[0]), "+f"(c[1]), "+f"(c[2]), "+f"(c[3])
        : "r"(a0), "r"(a1), "r"(a2), "r"(a3), "r"(b0), "r"(b1));
}

// ---------------- GEMM: C[m][n] = sum_k A[m][k] * W[n][k] ----------------
// block 128x128, warp 64x32, 3-stage cp.async, ldmatrix + register cvt
#define GBM 128
#define GBN 128
#define GBK 32
#define GST (GBK + 4)                         // 36-float row stride (mod 32 = 4 -> LDSM conflict-free)
#define GSTG (GBM * GST)
#define GNS 3
#define GSMEM (2 * GNS * GSTG * 4)            // 110592 B

__global__ __launch_bounds__(256, 2)
void gemm_nt(const float* __restrict__ A0, const float* __restrict__ A1, const float* __restrict__ A2,
             const float* __restrict__ W0, const float* __restrict__ W1, const float* __restrict__ W2,
             float* __restrict__ C0, float* __restrict__ C1, float* __restrict__ C2,
             int roundOut) {
    extern __shared__ float gsm[];
    float* Asm = gsm;
    float* Bsm = gsm + GNS * GSTG;

    const int z = blockIdx.z;
    const float* A = (z == 0) ? A0 : (z == 1) ? A1 : A2;
    const float* W = (z == 0) ? W0 : (z == 1) ? W1 : W2;
    float*       C = (z == 0) ? C0 : (z == 1) ? C1 : C2;

    const int m0 = blockIdx.y * GBM;
    const int n0 = blockIdx.x * GBN;
    const int tid = threadIdx.x;
    const int w = tid >> 5, lane = tid & 31;
    const int g = lane >> 2, tig = lane & 3;
    const int wm = (w >> 2) * 64;
    const int wn = (w & 3) * 32;

    const int lr = tid >> 3;
    const int lc = (tid & 7) << 2;

    const uint32_t sA = (uint32_t)__cvta_generic_to_shared(Asm);
    const uint32_t sB = (uint32_t)__cvta_generic_to_shared(Bsm);

    // ldmatrix per-thread address components
    const int lane7 = lane & 7;
    const int a_ro = ((lane >> 3) & 1) * 8;
    const int a_ko = ((lane >> 4) & 1) * 4;
    const int b_no = ((lane >> 4) & 1) * 8;
    const int b_ko = ((lane >> 3) & 1) * 4;

    uint32_t aIdx[4];
#pragma unroll
    for (int mt = 0; mt < 4; mt++)
        aIdx[mt] = (uint32_t)(((wm + mt * 16 + a_ro + lane7) * GST + a_ko) * 4);
    const uint32_t bIdx = (uint32_t)(((wn + b_no + lane7) * GST + b_ko) * 4);

    float acc[4][4][4];
#pragma unroll
    for (int i = 0; i < 4; i++)
#pragma unroll
        for (int j = 0; j < 4; j++)
#pragma unroll
            for (int e = 0; e < 4; e++) acc[i][j][e] = 0.f;

    auto issue = [&](int st, int k0) {
#pragma unroll
        for (int it = 0; it < 4; it++) {
            int row = lr + it * 32;
            cp16(sA + (uint32_t)((st * GBM + row) * GST + lc) * 4,
                 &A[(size_t)(m0 + row) * DDIM + k0 + lc]);
            cp16(sB + (uint32_t)((st * GBN + row) * GST + lc) * 4,
                 &W[(size_t)(n0 + row) * DDIM + k0 + lc]);
        }
    };

    issue(0, 0); cp_commit();
    issue(1, GBK); cp_commit();

    const int NKT = DDIM / GBK;       // 32
    for (int kt = 0; kt < NKT; kt++) {
        if (kt < NKT - 1) cp_wait<1>(); else cp_wait<0>();
        __syncthreads();

        const int st = kt % GNS;
        const uint32_t stb = (uint32_t)(st * GSTG * 4);

#pragma unroll
        for (int ks = 0; ks < 4; ks++) {
            const uint32_t ksB = (uint32_t)(ks * 32);   // 8 floats = 32 bytes
            uint32_t b[4][2];
            uint32_t bb = sB + stb + bIdx + ksB;
            ldsm4(b[0][0], b[0][1], b[1][0], b[1][1], bb);
            ldsm4(b[2][0], b[2][1], b[3][0], b[3][1], bb + 16 * GST * 4);
            uint32_t a[4][4];
#pragma unroll
            for (int mt = 0; mt < 4; mt++)
                ldsm4(a[mt][0], a[mt][1], a[mt][2], a[mt][3], sA + stb + aIdx[mt] + ksB);

#pragma unroll
            for (int nt = 0; nt < 4; nt++) {
                b[nt][0] = bits2tf32(b[nt][0]);
                b[nt][1] = bits2tf32(b[nt][1]);
            }
#pragma unroll
            for (int mt = 0; mt < 4; mt++) {
#pragma unroll
                for (int e = 0; e < 4; e++) a[mt][e] = bits2tf32(a[mt][e]);
#pragma unroll
                for (int nt = 0; nt < 4; nt++)
                    mma_tf32(acc[mt][nt], a[mt][0], a[mt][1], a[mt][2], a[mt][3],
                             b[nt][0], b[nt][1]);
            }
        }

        if (kt + 2 < NKT) {
            issue((kt + 2) % GNS, (kt + 2) * GBK);
            cp_commit();
        }
    }

#pragma unroll
    for (int mt = 0; mt < 4; mt++) {
        int r0 = m0 + wm + mt * 16 + g;
#pragma unroll
        for (int nt = 0; nt < 4; nt++) {
            int col = n0 + wn + nt * 8 + 2 * tig;
            float v0 = acc[mt][nt][0], v1 = acc[mt][nt][1];
            float v2 = acc[mt][nt][2], v3 = acc[mt][nt][3];
            if (roundOut) {
                v0 = __uint_as_float(f2tf32(v0)); v1 = __uint_as_float(f2tf32(v1));
                v2 = __uint_as_float(f2tf32(v2)); v3 = __uint_as_float(f2tf32(v3));
            }
            *reinterpret_cast<float2*>(&C[(size_t)r0 * DDIM + col]) = make_float2(v0, v1);
            *reinterpret_cast<float2*>(&C[(size_t)(r0 + 8) * DDIM + col]) = make_float2(v2, v3);
        }
    }
}

// ---------------- flash attention: rounded K/V from GEMM epilogue, ldmatrix frags,
// ---------------- cp.async double-buffer, all-valid mask fast path ----------------
#define AQT 128
#define AP 68    // mod 32 = 4 -> LDSM conflict-free
#define ASMEM ((2*64 + 2*64 + 128) * AP * 4 + 2 * 64 * 4)

__global__ __launch_bounds__(128, 1)
void attn_kernel(const float* __restrict__ Q, const float* __restrict__ K,
                 const float* __restrict__ V, const int* __restrict__ mask,
                 float* __restrict__ O) {
    extern __shared__ uint32_t smem_u[];
    uint32_t* Ks0 = smem_u;                      // 2 stages x 64 rows (tf32 bits)
    uint32_t* Vs0 = Ks0 + 2 * 64 * AP;
    uint32_t* Ps  = Vs0 + 2 * 64 * AP;           // 128 rows (Q staging + P)
    int* msk0 = (int*)(Ps + 128 * AP);

    const int qi = gridDim.x - 1 - blockIdx.x;   // heavy tiles first
    const int bh = blockIdx.y;
    const int b = bh / HH, h = bh % HH;

    const int tid = threadIdx.x;
    const int w = tid >> 5, lane = tid & 31;
    const int g = lane >> 2, tig = lane & 3;
    const int wrow = w * 32;

    const float* Qb = Q + ((size_t)b * SS + (size_t)qi * AQT) * DDIM + h * DKK;
    const float* Kb = K + (size_t)b * SS * DDIM + h * DKK;
    const float* Vb = V + (size_t)b * SS * DDIM + h * DKK;
    float* Ob = O + ((size_t)b * SS + (size_t)qi * AQT) * DDIM + h * DKK;

    const uint32_t sK = (uint32_t)__cvta_generic_to_shared(Ks0);
    const uint32_t sV = (uint32_t)__cvta_generic_to_shared(Vs0);
    const uint32_t sP = (uint32_t)__cvta_generic_to_shared(Ps);
    const uint32_t sM = (uint32_t)__cvta_generic_to_shared(msk0);

    const int lane7 = lane & 7;
    const int a_ro = ((lane >> 3) & 1) * 8;
    const int a_ko = ((lane >> 4) & 1) * 4;
    const int b_no = ((lane >> 4) & 1) * 8;
    const int b_ko = ((lane >> 3) & 1) * 4;

    const float qscale = 0.125f * 1.4426950408889634f;

    auto issueKV = [&](int st, int kt) {
        const float* Kt = Kb + (size_t)kt * 64 * DDIM;
        const float* Vt = Vb + (size_t)kt * 64 * DDIM;
#pragma unroll
        for (int t = 0; t < 8; t++) {
            int i = tid + t * 128;
            int r = i >> 4;
            int c4 = (i & 15) << 2;
            uint32_t off = (uint32_t)((st * 64 + r) * AP + c4) * 4;
            cp16(sK + off, Kt + (size_t)r * DDIM + c4);
            cp16(sV + off, Vt + (size_t)r * DDIM + c4);
        }
        if (tid < 64) cp4(sM + (uint32_t)(st * 64 + tid) * 4, &mask[(size_t)b * SS + kt * 64 + tid]);
    };

    const int ktmax = 2 * qi + 1;
    issueKV(0, 0);
    cp_commit();

    // stage Q (128x64), scale+round, then pull fragments via ldmatrix
#pragma unroll
    for (int t = 0; t < 16; t++) {
        int i = tid + t * 128;
        int r = i >> 4;
        int c4 = (i & 15) << 2;
        float4 v = *reinterpret_cast<const float4*>(Qb + (size_t)r * DDIM + c4);
        uint32_t* p = &Ps[r * AP + c4];
        p[0] = f2tf32(v.x * qscale); p[1] = f2tf32(v.y * qscale);
        p[2] = f2tf32(v.z * qscale); p[3] = f2tf32(v.w * qscale);
    }
    __syncthreads();

    uint32_t qf[2][8][4];
#pragma unroll
    for (int mt = 0; mt < 2; mt++) {
        const uint32_t base = sP + (uint32_t)(((wrow + mt * 16 + a_ro + lane7) * AP + a_ko) * 4);
#pragma unroll
        for (int ks = 0; ks < 8; ks++)
            ldsm4(qf[mt][ks][0], qf[mt][ks][1], qf[mt][ks][2], qf[mt][ks][3],
                  base + (uint32_t)(ks * 32));
    }

    float mrow[2][2], lrow[2][2];
    float o[2][8][4];
#pragma unroll
    for (int mt = 0; mt < 2; mt++) {
        mrow[mt][0] = mrow[mt][1] = -1e30f;
        lrow[mt][0] = lrow[mt][1] = 0.f;
#pragma unroll
        for (int nt = 0; nt < 8; nt++)
#pragma unroll
            for (int e = 0; e < 4; e++) o[mt][nt][e] = 0.f;
    }

    const int rowmax = qi * AQT + wrow + 31;

    for (int kt = 0; kt <= ktmax; kt++) {
        const int cur = kt & 1;
        __syncthreads();
        if (kt < ktmax) {
            issueKV(cur ^ 1, kt + 1);
            cp_commit();
            cp_wait<1>();
        } else {
            cp_wait<0>();
        }
        __syncthreads();

        const uint32_t sKst = sK + (uint32_t)(cur * 64 * AP * 4);
        const uint32_t* Vsr = Vs0 + cur * 64 * AP;
        const int* msk = msk0 + cur * 64;

        if (kt * 64 > rowmax) continue;

        // all-valid padding-mask fast path (warp-uniform)
        const int mvl0 = msk[lane], mvl1 = msk[32 + lane];
        const bool allvalid = __all_sync(0xffffffffu, (mvl0 != 0) && (mvl1 != 0));

        // S = Q @ K^T : 32x64 per warp, K frags via ldmatrix (raw rounded bits)
        float s[2][8][4];
#pragma unroll
        for (int mt = 0; mt < 2; mt++)
#pragma unroll
            for (int nt = 0; nt < 8; nt++)
                s[mt][nt][0] = s[mt][nt][1] = s[mt][nt][2] = s[mt][nt][3] = 0.f;

        const uint32_t kb0 = sKst + (uint32_t)(((b_no + lane7) * AP + b_ko) * 4);
#pragma unroll
        for (int ks = 0; ks < 8; ks++) {
            const uint32_t ksB = (uint32_t)(ks * 32);
            uint32_t bf[8][2];
#pragma unroll
            for (int j = 0; j < 4; j++)
                ldsm4(bf[2*j][0], bf[2*j][1], bf[2*j+1][0], bf[2*j+1][1],
                      kb0 + (uint32_t)(j * 16 * AP * 4) + ksB);
#pragma unroll
            for (int mt = 0; mt < 2; mt++)
#pragma unroll
                for (int nt = 0; nt < 8; nt++)
                    mma_tf32(s[mt][nt], qf[mt][ks][0], qf[mt][ks][1],
                             qf[mt][ks][2], qf[mt][ks][3], bf[nt][0], bf[nt][1]);
        }

        // masking + online softmax
#pragma unroll
        for (int mt = 0; mt < 2; mt++) {
            const int q0 = qi * AQT + wrow + mt * 16 + g;
            const int q1 = q0 + 8;
            const bool needc = (kt * 64 + 63 > qi * AQT + wrow + mt * 16);

            if (!allvalid) {
#pragma unroll
                for (int nt = 0; nt < 8; nt++) {
                    int cl = nt * 8 + 2 * tig;
                    int cg = kt * 64 + cl;
                    bool mv0 = (msk[cl] != 0);
                    bool mv1 = (msk[cl + 1] != 0);
                    if (!mv0 || (needc && cg > q0))     s[mt][nt][0] = -1e30f;
                    if (!mv1 || (needc && cg + 1 > q0)) s[mt][nt][1] = -1e30f;
                    if (!mv0 || (needc && cg > q1))     s[mt][nt][2] = -1e30f;
                    if (!mv1 || (needc && cg + 1 > q1)) s[mt][nt][3] = -1e30f;
                }
            } else if (needc) {
#pragma unroll
                for (int nt = 0; nt < 8; nt++) {
                    int cg = kt * 64 + nt * 8 + 2 * tig;
                    if (cg > q0)     s[mt][nt][0] = -1e30f;
                    if (cg + 1 > q0) s[mt][nt][1] = -1e30f;
                    if (cg > q1)     s[mt][nt][2] = -1e30f;
                    if (cg + 1 > q1) s[mt][nt][3] = -1e30f;
                }
            }

            float rm0 = -1e30f, rm1 = -1e30f;
#pragma unroll
            for (int nt = 0; nt < 8; nt++) {
                rm0 = fmaxf(rm0, fmaxf(s[mt][nt][0], s[mt][nt][1]));
                rm1 = fmaxf(rm1, fmaxf(s[mt][nt][2], s[mt][nt][3]));
            }
            rm0 = fmaxf(rm0, __shfl_xor_sync(0xffffffffu, rm0, 1));
            rm0 = fmaxf(rm0, __shfl_xor_sync(0xffffffffu, rm0, 2));
            rm1 = fmaxf(rm1, __shfl_xor_sync(0xffffffffu, rm1, 1));
            rm1 = fmaxf(rm1, __shfl_xor_sync(0xffffffffu, rm1, 2));

            float mn0 = fmaxf(mrow[mt][0], rm0);
            float mn1 = fmaxf(mrow[mt][1], rm1);
            float al0 = ex2(mrow[mt][0] - mn0);
            float al1 = ex2(mrow[mt][1] - mn1);
            mrow[mt][0] = mn0; mrow[mt][1] = mn1;

            float rs0 = 0.f, rs1 = 0.f;
            const int pr = wrow + mt * 16;
#pragma unroll
            for (int nt = 0; nt < 8; nt++) {
                int cl = nt * 8 + 2 * tig;
                float p0 = ex2(s[mt][nt][0] - mn0);
                float p1 = ex2(s[mt][nt][1] - mn0);
                float p2 = ex2(s[mt][nt][2] - mn1);
                float p3 = ex2(s[mt][nt][3] - mn1);
                rs0 += p0 + p1;
                rs1 += p2 + p3;
                Ps[(pr + g) * AP + cl]         = f2tf32(p0);
                Ps[(pr + g) * AP + cl + 1]     = f2tf32(p1);
                Ps[(pr + g + 8) * AP + cl]     = f2tf32(p2);
                Ps[(pr + g + 8) * AP + cl + 1] = f2tf32(p3);
            }
            rs0 += __shfl_xor_sync(0xffffffffu, rs0, 1);
            rs0 += __shfl_xor_sync(0xffffffffu, rs0, 2);
            rs1 += __shfl_xor_sync(0xffffffffu, rs1, 1);
            rs1 += __shfl_xor_sync(0xffffffffu, rs1, 2);
            lrow[mt][0] = lrow[mt][0] * al0 + rs0;
            lrow[mt][1] = lrow[mt][1] * al1 + rs1;

#pragma unroll
            for (int nt = 0; nt < 8; nt++) {
                o[mt][nt][0] *= al0; o[mt][nt][1] *= al0;
                o[mt][nt][2] *= al1; o[mt][nt][3] *= al1;
            }
        }
        __syncwarp();

        // O += P @ V : P frags via ldmatrix, V raw (rounded bits)
#pragma unroll
        for (int ks = 0; ks < 8; ks++) {
            int kk = ks * 8;
            uint32_t vb[8][2];
#pragma unroll
            for (int nt = 0; nt < 8; nt++) {
                vb[nt][0] = Vsr[(kk + tig) * AP + nt * 8 + g];
                vb[nt][1] = Vsr[(kk + tig + 4) * AP + nt * 8 + g];
            }
#pragma unroll
            for (int mt = 0; mt < 2; mt++) {
                const int pr = wrow + mt * 16;
                uint32_t a0, a1, a2, a3;
                ldsm4(a0, a1, a2, a3,
                      sP + (uint32_t)(((pr + a_ro + lane7) * AP + kk + a_ko) * 4));
#pragma unroll
                for (int nt = 0; nt < 8; nt++)
                    mma_tf32(o[mt][nt], a0, a1, a2, a3, vb[nt][0], vb[nt][1]);
            }
        }
    }

    // normalize + store (rounded: feeds the Wo tf32 GEMM)
#pragma unroll
    for (int mt = 0; mt < 2; mt++) {
        float i0 = 1.f / lrow[mt][0];
        float i1 = 1.f / lrow[mt][1];
        int r0 = wrow + mt * 16 + g;
#pragma unroll
        for (int nt = 0; nt < 8; nt++) {
            int cl = nt * 8 + 2 * tig;
            *reinterpret_cast<float2*>(&Ob[(size_t)r0 * DDIM + cl]) =
                make_float2(__uint_as_float(f2tf32(o[mt][nt][0] * i0)),
                            __uint_as_float(f2tf32(o[mt][nt][1] * i0)));
            *reinterpret_cast<float2*>(&Ob[(size_t)(r0 + 8) * DDIM + cl]) =
                make_float2(__uint_as_float(f2tf32(o[mt][nt][2] * i1)),
                            __uint_as_float(f2tf32(o[mt][nt][3] * i1)));
        }
    }
}

// ---------------- launch ----------------
extern "C" void kernel_launch(void* const* d_in, const int* in_sizes, int n_in,
                              void* d_out, int out_size) {
    const float* xq = (const float*)d_in[0];
    const float* xk = (const float*)d_in[1];
    const float* xv = (const float*)d_in[2];
    const int* mask = (const int*)d_in[3];
    const float* Wq = (const float*)d_in[4];
    const float* Wk = (const float*)d_in[5];
    const float* Wv = (const float*)d_in[6];
    const float* Wo = (const float*)d_in[7];
    float* out = (float*)d_out;

    float *Qp, *Kp, *Vp, *Ap;
    cudaGetSymbolAddress((void**)&Qp, g_Q);
    cudaGetSymbolAddress((void**)&Kp, g_K);
    cudaGetSymbolAddress((void**)&Vp, g_V);
    cudaGetSymbolAddress((void**)&Ap, g_A);

    cudaFuncSetAttribute(gemm_nt, cudaFuncAttributeMaxDynamicSharedMemorySize, GSMEM);
    cudaFuncSetAttribute(attn_kernel, cudaFuncAttributeMaxDynamicSharedMemorySize, ASMEM);

    // fused QKV projections; outputs rounded to tf32 for attention consumption
    gemm_nt<<<dim3(DDIM / GBN, MTOT / GBM, 3), 256, GSMEM>>>(
        xq, xk, xv, Wq, Wk, Wv, Qp, Kp, Vp, 1);

    attn_kernel<<<dim3(SS / AQT, BB * HH), 128, ASMEM>>>(Qp, Kp, Vp, mask, Ap);

    // output projection; exact fp32 output
    gemm_nt<<<dim3(DDIM / GBN, MTOT / GBM, 1), 256, GSMEM>>>(
        Ap, Ap, Ap, Wo, Wo, Wo, out, out, out, 0);
}

// round 8
// speedup vs baseline: 1.1819x; 1.0154x over previous
#include <cuda_runtime.h>
#include <cstdint>

#define BB 4
#define SS 2048
#define DDIM 1024
#define HH 16
#define DKK 64
#define MTOT (BB*SS)   // 8192

// ---------------- scratch (static __device__, allocation-free) ----------------
__device__ float g_Q[(size_t)MTOT*DDIM];
__device__ float g_K[(size_t)MTOT*DDIM];
__device__ float g_V[(size_t)MTOT*DDIM];
__device__ float g_A[(size_t)MTOT*DDIM];

// ---------------- helpers ----------------
__device__ __forceinline__ uint32_t f2tf32(float f) {
    uint32_t u;
    asm("cvt.rna.tf32.f32 %0, %1;" : "=r"(u) : "f"(f));
    return u;
}
__device__ __forceinline__ uint32_t bits2tf32(uint32_t b) {
    return f2tf32(__uint_as_float(b));
}
__device__ __forceinline__ float ex2(float x) {
    float y;
    asm("ex2.approx.ftz.f32 %0, %1;" : "=f"(y) : "f"(x));
    return y;
}
__device__ __forceinline__ void cp16(uint32_t saddr, const void* g) {
    asm volatile("cp.async.cg.shared.global [%0], [%1], 16;" :: "r"(saddr), "l"(g));
}
__device__ __forceinline__ void cp4(uint32_t saddr, const void* g) {
    asm volatile("cp.async.ca.shared.global [%0], [%1], 4;" :: "r"(saddr), "l"(g));
}
__device__ __forceinline__ void cp_commit() {
    asm volatile("cp.async.commit_group;");
}
template <int N>
__device__ __forceinline__ void cp_wait() {
    asm volatile("cp.async.wait_group %0;" :: "n"(N));
}
// 8x8 tf32 tile == one b16 ldmatrix unit (8 rows x 16B); thread t gets (row t/4, col t%4)
__device__ __forceinline__ void ldsm4(uint32_t& r0, uint32_t& r1, uint32_t& r2, uint32_t& r3,
                                      uint32_t addr) {
    asm volatile("ldmatrix.sync.aligned.m8n8.x4.shared.b16 {%0,%1,%2,%3}, [%4];"
                 : "=r"(r0), "=r"(r1), "=r"(r2), "=r"(r3) : "r"(addr));
}

// D(16x8,f32) += A(16x8,tf32,row) * B(8x8,tf32,col)
__device__ __forceinline__ void mma_tf32(float c[4],
                                         uint32_t a0, uint32_t a1, uint32_t a2, uint32_t a3,
                                         uint32_t b0, uint32_t b1) {
    asm volatile(
        "mma.sync.aligned.m16n8k8.row.col.f32.tf32.tf32.f32 "
        "{%0,%1,%2,%3}, {%4,%5,%6,%7}, {%8,%9}, {%0,%1,%2,%3};"
        : "+f"(c[0]), "+f"(c[1]), "+f"(c[2]), "+f"(c[3])
        : "r"(a0), "r"(a1), "r"(a2), "r"(a3), "r"(b0), "r"(b1));
}

// ---------------- GEMM: C[m][n] = sum_k A[m][k] * W[n][k] ----------------
// block 128x128, warp 64x32, 3-stage cp.async, ldmatrix + register cvt (R7, proven)
#define GBM 128
#define GBN 128
#define GBK 32
#define GST (GBK + 4)
#define GSTG (GBM * GST)
#define GNS 3
#define GSMEM (2 * GNS * GSTG * 4)            // 110592 B

__global__ __launch_bounds__(256, 2)
void gemm_nt(const float* __restrict__ A0, const float* __restrict__ A1, const float* __restrict__ A2,
             const float* __restrict__ W0, const float* __restrict__ W1, const float* __restrict__ W2,
             float* __restrict__ C0, float* __restrict__ C1, float* __restrict__ C2,
             int roundOut) {
    extern __shared__ float gsm[];
    float* Asm = gsm;
    float* Bsm = gsm + GNS * GSTG;

    const int z = blockIdx.z;
    const float* A = (z == 0) ? A0 : (z == 1) ? A1 : A2;
    const float* W = (z == 0) ? W0 : (z == 1) ? W1 : W2;
    float*       C = (z == 0) ? C0 : (z == 1) ? C1 : C2;

    const int m0 = blockIdx.y * GBM;
    const int n0 = blockIdx.x * GBN;
    const int tid = threadIdx.x;
    const int w = tid >> 5, lane = tid & 31;
    const int g = lane >> 2, tig = lane & 3;
    const int wm = (w >> 2) * 64;
    const int wn = (w & 3) * 32;

    const int lr = tid >> 3;
    const int lc = (tid & 7) << 2;

    const uint32_t sA = (uint32_t)__cvta_generic_to_shared(Asm);
    const uint32_t sB = (uint32_t)__cvta_generic_to_shared(Bsm);

    const int lane7 = lane & 7;
    const int a_ro = ((lane >> 3) & 1) * 8;
    const int a_ko = ((lane >> 4) & 1) * 4;
    const int b_no = ((lane >> 4) & 1) * 8;
    const int b_ko = ((lane >> 3) & 1) * 4;

    uint32_t aIdx[4];
#pragma unroll
    for (int mt = 0; mt < 4; mt++)
        aIdx[mt] = (uint32_t)(((wm + mt * 16 + a_ro + lane7) * GST + a_ko) * 4);
    const uint32_t bIdx = (uint32_t)(((wn + b_no + lane7) * GST + b_ko) * 4);

    float acc[4][4][4];
#pragma unroll
    for (int i = 0; i < 4; i++)
#pragma unroll
        for (int j = 0; j < 4; j++)
#pragma unroll
            for (int e = 0; e < 4; e++) acc[i][j][e] = 0.f;

    auto issue = [&](int st, int k0) {
#pragma unroll
        for (int it = 0; it < 4; it++) {
            int row = lr + it * 32;
            cp16(sA + (uint32_t)((st * GBM + row) * GST + lc) * 4,
                 &A[(size_t)(m0 + row) * DDIM + k0 + lc]);
            cp16(sB + (uint32_t)((st * GBN + row) * GST + lc) * 4,
                 &W[(size_t)(n0 + row) * DDIM + k0 + lc]);
        }
    };

    issue(0, 0); cp_commit();
    issue(1, GBK); cp_commit();

    const int NKT = DDIM / GBK;
    for (int kt = 0; kt < NKT; kt++) {
        if (kt < NKT - 1) cp_wait<1>(); else cp_wait<0>();
        __syncthreads();

        const int st = kt % GNS;
        const uint32_t stb = (uint32_t)(st * GSTG * 4);

#pragma unroll
        for (int ks = 0; ks < 4; ks++) {
            const uint32_t ksB = (uint32_t)(ks * 32);
            uint32_t b[4][2];
            uint32_t bb = sB + stb + bIdx + ksB;
            ldsm4(b[0][0], b[0][1], b[1][0], b[1][1], bb);
            ldsm4(b[2][0], b[2][1], b[3][0], b[3][1], bb + 16 * GST * 4);
            uint32_t a[4][4];
#pragma unroll
            for (int mt = 0; mt < 4; mt++)
                ldsm4(a[mt][0], a[mt][1], a[mt][2], a[mt][3], sA + stb + aIdx[mt] + ksB);

#pragma unroll
            for (int nt = 0; nt < 4; nt++) {
                b[nt][0] = bits2tf32(b[nt][0]);
                b[nt][1] = bits2tf32(b[nt][1]);
            }
#pragma unroll
            for (int mt = 0; mt < 4; mt++) {
#pragma unroll
                for (int e = 0; e < 4; e++) a[mt][e] = bits2tf32(a[mt][e]);
#pragma unroll
                for (int nt = 0; nt < 4; nt++)
                    mma_tf32(acc[mt][nt], a[mt][0], a[mt][1], a[mt][2], a[mt][3],
                             b[nt][0], b[nt][1]);
            }
        }

        if (kt + 2 < NKT) {
            issue((kt + 2) % GNS, (kt + 2) * GBK);
            cp_commit();
        }
    }

#pragma unroll
    for (int mt = 0; mt < 4; mt++) {
        int r0 = m0 + wm + mt * 16 + g;
#pragma unroll
        for (int nt = 0; nt < 4; nt++) {
            int col = n0 + wn + nt * 8 + 2 * tig;
            float v0 = acc[mt][nt][0], v1 = acc[mt][nt][1];
            float v2 = acc[mt][nt][2], v3 = acc[mt][nt][3];
            if (roundOut) {
                v0 = __uint_as_float(f2tf32(v0)); v1 = __uint_as_float(f2tf32(v1));
                v2 = __uint_as_float(f2tf32(v2)); v3 = __uint_as_float(f2tf32(v3));
            }
            *reinterpret_cast<float2*>(&C[(size_t)r0 * DDIM + col]) = make_float2(v0, v1);
            *reinterpret_cast<float2*>(&C[(size_t)(r0 + 8) * DDIM + col]) = make_float2(v2, v3);
        }
    }
}

// ---------------- flash attention: 256-row Q tile, 8 warps, cp.async double-buffer ----------------
#define AQT 256
#define ATHR 256
#define AP 68    // K/P stride: 272B mod 128 = 16 -> LDSM conflict-free
#define VP 72    // V stride: 72 mod 32 = 8 -> scalar B-frag loads conflict-free
#define ASMEM ((2*64*AP + 2*64*VP + AQT*AP) * 4 + 2 * 64 * 4)   // 141824 B

__global__ __launch_bounds__(ATHR, 1)
void attn_kernel(const float* __restrict__ Q, const float* __restrict__ K,
                 const float* __restrict__ V, const int* __restrict__ mask,
                 float* __restrict__ O) {
    extern __shared__ uint32_t smem_u[];
    uint32_t* Ks0 = smem_u;                      // 2 stages x 64 rows (stride AP)
    uint32_t* Vs0 = Ks0 + 2 * 64 * AP;           // 2 stages x 64 rows (stride VP)
    uint32_t* Ps  = Vs0 + 2 * 64 * VP;           // AQT rows (Q staging + P), stride AP
    int* msk0 = (int*)(Ps + AQT * AP);

    const int qi = gridDim.x - 1 - blockIdx.x;   // heavy tiles first
    const int bh = blockIdx.y;
    const int b = bh / HH, h = bh % HH;

    const int tid = threadIdx.x;
    const int w = tid >> 5, lane = tid & 31;
    const int g = lane >> 2, tig = lane & 3;
    const int wrow = w * 32;

    const float* Qb = Q + ((size_t)b * SS + (size_t)qi * AQT) * DDIM + h * DKK;
    const float* Kb = K + (size_t)b * SS * DDIM + h * DKK;
    const float* Vb = V + (size_t)b * SS * DDIM + h * DKK;
    float* Ob = O + ((size_t)b * SS + (size_t)qi * AQT) * DDIM + h * DKK;

    const uint32_t sK = (uint32_t)__cvta_generic_to_shared(Ks0);
    const uint32_t sV = (uint32_t)__cvta_generic_to_shared(Vs0);
    const uint32_t sP = (uint32_t)__cvta_generic_to_shared(Ps);
    const uint32_t sM = (uint32_t)__cvta_generic_to_shared(msk0);

    const int lane7 = lane & 7;
    const int a_ro = ((lane >> 3) & 1) * 8;
    const int a_ko = ((lane >> 4) & 1) * 4;
    const int b_no = ((lane >> 4) & 1) * 8;
    const int b_ko = ((lane >> 3) & 1) * 4;

    const float qscale = 0.125f * 1.4426950408889634f;

    auto issueKV = [&](int st, int kt) {
        const float* Kt = Kb + (size_t)kt * 64 * DDIM;
        const float* Vt = Vb + (size_t)kt * 64 * DDIM;
#pragma unroll
        for (int t = 0; t < 4; t++) {
            int i = tid + t * ATHR;
            int r = i >> 4;
            int c4 = (i & 15) << 2;
            cp16(sK + (uint32_t)((st * 64 + r) * AP + c4) * 4, Kt + (size_t)r * DDIM + c4);
            cp16(sV + (uint32_t)((st * 64 + r) * VP + c4) * 4, Vt + (size_t)r * DDIM + c4);
        }
        if (tid < 64) cp4(sM + (uint32_t)(st * 64 + tid) * 4, &mask[(size_t)b * SS + kt * 64 + tid]);
    };

    const int ktmax = (AQT / 64) * qi + (AQT / 64) - 1;   // 4*qi + 3
    issueKV(0, 0);
    cp_commit();

    // stage Q (AQT x 64), scale+round, then pull fragments via ldmatrix
#pragma unroll
    for (int t = 0; t < 16; t++) {
        int i = tid + t * ATHR;
        int r = i >> 4;
        int c4 = (i & 15) << 2;
        float4 v = *reinterpret_cast<const float4*>(Qb + (size_t)r * DDIM + c4);
        uint32_t* p = &Ps[r * AP + c4];
        p[0] = f2tf32(v.x * qscale); p[1] = f2tf32(v.y * qscale);
        p[2] = f2tf32(v.z * qscale); p[3] = f2tf32(v.w * qscale);
    }
    __syncthreads();

    uint32_t qf[2][8][4];
#pragma unroll
    for (int mt = 0; mt < 2; mt++) {
        const uint32_t base = sP + (uint32_t)(((wrow + mt * 16 + a_ro + lane7) * AP + a_ko) * 4);
#pragma unroll
        for (int ks = 0; ks < 8; ks++)
            ldsm4(qf[mt][ks][0], qf[mt][ks][1], qf[mt][ks][2], qf[mt][ks][3],
                  base + (uint32_t)(ks * 32));
    }

    float mrow[2][2], lrow[2][2];
    float o[2][8][4];
#pragma unroll
    for (int mt = 0; mt < 2; mt++) {
        mrow[mt][0] = mrow[mt][1] = -1e30f;
        lrow[mt][0] = lrow[mt][1] = 0.f;
#pragma unroll
        for (int nt = 0; nt < 8; nt++)
#pragma unroll
            for (int e = 0; e < 4; e++) o[mt][nt][e] = 0.f;
    }

    const int rowmax = qi * AQT + wrow + 31;

    for (int kt = 0; kt <= ktmax; kt++) {
        const int cur = kt & 1;
        __syncthreads();
        if (kt < ktmax) {
            issueKV(cur ^ 1, kt + 1);
            cp_commit();
            cp_wait<1>();
        } else {
            cp_wait<0>();
        }
        __syncthreads();

        const uint32_t sKst = sK + (uint32_t)(cur * 64 * AP * 4);
        const uint32_t* Vsr = Vs0 + cur * 64 * VP;
        const int* msk = msk0 + cur * 64;

        if (kt * 64 > rowmax) continue;

        const int mvl0 = msk[lane], mvl1 = msk[32 + lane];
        const bool allvalid = __all_sync(0xffffffffu, (mvl0 != 0) && (mvl1 != 0));

        // S = Q @ K^T : 32x64 per warp
        float s[2][8][4];
#pragma unroll
        for (int mt = 0; mt < 2; mt++)
#pragma unroll
            for (int nt = 0; nt < 8; nt++)
                s[mt][nt][0] = s[mt][nt][1] = s[mt][nt][2] = s[mt][nt][3] = 0.f;

        const uint32_t kb0 = sKst + (uint32_t)(((b_no + lane7) * AP + b_ko) * 4);
#pragma unroll
        for (int ks = 0; ks < 8; ks++) {
            const uint32_t ksB = (uint32_t)(ks * 32);
            uint32_t bf[8][2];
#pragma unroll
            for (int j = 0; j < 4; j++)
                ldsm4(bf[2*j][0], bf[2*j][1], bf[2*j+1][0], bf[2*j+1][1],
                      kb0 + (uint32_t)(j * 16 * AP * 4) + ksB);
#pragma unroll
            for (int mt = 0; mt < 2; mt++)
#pragma unroll
                for (int nt = 0; nt < 8; nt++)
                    mma_tf32(s[mt][nt], qf[mt][ks][0], qf[mt][ks][1],
                             qf[mt][ks][2], qf[mt][ks][3], bf[nt][0], bf[nt][1]);
        }

        // masking + online softmax
#pragma unroll
        for (int mt = 0; mt < 2; mt++) {
            const int q0 = qi * AQT + wrow + mt * 16 + g;
            const int q1 = q0 + 8;
            const bool needc = (kt * 64 + 63 > qi * AQT + wrow + mt * 16);

            if (!allvalid) {
#pragma unroll
                for (int nt = 0; nt < 8; nt++) {
                    int cl = nt * 8 + 2 * tig;
                    int cg = kt * 64 + cl;
                    bool mv0 = (msk[cl] != 0);
                    bool mv1 = (msk[cl + 1] != 0);
                    if (!mv0 || (needc && cg > q0))     s[mt][nt][0] = -1e30f;
                    if (!mv1 || (needc && cg + 1 > q0)) s[mt][nt][1] = -1e30f;
                    if (!mv0 || (needc && cg > q1))     s[mt][nt][2] = -1e30f;
                    if (!mv1 || (needc && cg + 1 > q1)) s[mt][nt][3] = -1e30f;
                }
            } else if (needc) {
#pragma unroll
                for (int nt = 0; nt < 8; nt++) {
                    int cg = kt * 64 + nt * 8 + 2 * tig;
                    if (cg > q0)     s[mt][nt][0] = -1e30f;
                    if (cg + 1 > q0) s[mt][nt][1] = -1e30f;
                    if (cg > q1)     s[mt][nt][2] = -1e30f;
                    if (cg + 1 > q1) s[mt][nt][3] = -1e30f;
                }
            }

            float rm0 = -1e30f, rm1 = -1e30f;
#pragma unroll
            for (int nt = 0; nt < 8; nt++) {
                rm0 = fmaxf(rm0, fmaxf(s[mt][nt][0], s[mt][nt][1]));
                rm1 = fmaxf(rm1, fmaxf(s[mt][nt][2], s[mt][nt][3]));
            }
            rm0 = fmaxf(rm0, __shfl_xor_sync(0xffffffffu, rm0, 1));
            rm0 = fmaxf(rm0, __shfl_xor_sync(0xffffffffu, rm0, 2));
            rm1 = fmaxf(rm1, __shfl_xor_sync(0xffffffffu, rm1, 1));
            rm1 = fmaxf(rm1, __shfl_xor_sync(0xffffffffu, rm1, 2));

            float mn0 = fmaxf(mrow[mt][0], rm0);
            float mn1 = fmaxf(mrow[mt][1], rm1);
            float al0 = ex2(mrow[mt][0] - mn0);
            float al1 = ex2(mrow[mt][1] - mn1);
            mrow[mt][0] = mn0; mrow[mt][1] = mn1;

            float rs0 = 0.f, rs1 = 0.f;
            const int pr = wrow + mt * 16;
#pragma unroll
            for (int nt = 0; nt < 8; nt++) {
                int cl = nt * 8 + 2 * tig;
                float p0 = ex2(s[mt][nt][0] - mn0);
                float p1 = ex2(s[mt][nt][1] - mn0);
                float p2 = ex2(s[mt][nt][2] - mn1);
                float p3 = ex2(s[mt][nt][3] - mn1);
                rs0 += p0 + p1;
                rs1 += p2 + p3;
                Ps[(pr + g) * AP + cl]         = f2tf32(p0);
                Ps[(pr + g) * AP + cl + 1]     = f2tf32(p1);
                Ps[(pr + g + 8) * AP + cl]     = f2tf32(p2);
                Ps[(pr + g + 8) * AP + cl + 1] = f2tf32(p3);
            }
            rs0 += __shfl_xor_sync(0xffffffffu, rs0, 1);
            rs0 += __shfl_xor_sync(0xffffffffu, rs0, 2);
            rs1 += __shfl_xor_sync(0xffffffffu, rs1, 1);
            rs1 += __shfl_xor_sync(0xffffffffu, rs1, 2);
            lrow[mt][0] = lrow[mt][0] * al0 + rs0;
            lrow[mt][1] = lrow[mt][1] * al1 + rs1;

#pragma unroll
            for (int nt = 0; nt < 8; nt++) {
                o[mt][nt][0] *= al0; o[mt][nt][1] *= al0;
                o[mt][nt][2] *= al1; o[mt][nt][3] *= al1;
            }
        }
        __syncwarp();

        // O += P @ V : P frags via ldmatrix, V scalar (conflict-free at stride 72)
#pragma unroll
        for (int ks = 0; ks < 8; ks++) {
            int kk = ks * 8;
            uint32_t vb[8][2];
#pragma unroll
            for (int nt = 0; nt < 8; nt++) {
                vb[nt][0] = Vsr[(kk + tig) * VP + nt * 8 + g];
                vb[nt][1] = Vsr[(kk + tig + 4) * VP + nt * 8 + g];
            }
#pragma unroll
            for (int mt = 0; mt < 2; mt++) {
                const int pr = wrow + mt * 16;
                uint32_t a0, a1, a2, a3;
                ldsm4(a0, a1, a2, a3,
                      sP + (uint32_t)(((pr + a_ro + lane7) * AP + kk + a_ko) * 4));
#pragma unroll
                for (int nt = 0; nt < 8; nt++)
                    mma_tf32(o[mt][nt], a0, a1, a2, a3, vb[nt][0], vb[nt][1]);
            }
        }
    }

    // normalize + store (rounded: feeds the Wo tf32 GEMM)
#pragma unroll
    for (int mt = 0; mt < 2; mt++) {
        float i0 = 1.f / lrow[mt][0];
        float i1 = 1.f / lrow[mt][1];
        int r0 = wrow + mt * 16 + g;
#pragma unroll
        for (int nt = 0; nt < 8; nt++) {
            int cl = nt * 8 + 2 * tig;
            *reinterpret_cast<float2*>(&Ob[(size_t)r0 * DDIM + cl]) =
                make_float2(__uint_as_float(f2tf32(o[mt][nt][0] * i0)),
                            __uint_as_float(f2tf32(o[mt][nt][1] * i0)));
            *reinterpret_cast<float2*>(&Ob[(size_t)(r0 + 8) * DDIM + cl]) =
                make_float2(__uint_as_float(f2tf32(o[mt][nt][2] * i1)),
                            __uint_as_float(f2tf32(o[mt][nt][3] * i1)));
        }
    }
}

// ---------------- launch ----------------
extern "C" void kernel_launch(void* const* d_in, const int* in_sizes, int n_in,
                              void* d_out, int out_size) {
    const float* xq = (const float*)d_in[0];
    const float* xk = (const float*)d_in[1];
    const float* xv = (const float*)d_in[2];
    const int* mask = (const int*)d_in[3];
    const float* Wq = (const float*)d_in[4];
    const float* Wk = (const float*)d_in[5];
    const float* Wv = (const float*)d_in[6];
    const float* Wo = (const float*)d_in[7];
    float* out = (float*)d_out;

    float *Qp, *Kp, *Vp, *Ap;
    cudaGetSymbolAddress((void**)&Qp, g_Q);
    cudaGetSymbolAddress((void**)&Kp, g_K);
    cudaGetSymbolAddress((void**)&Vp, g_V);
    cudaGetSymbolAddress((void**)&Ap, g_A);

    cudaFuncSetAttribute(gemm_nt, cudaFuncAttributeMaxDynamicSharedMemorySize, GSMEM);
    cudaFuncSetAttribute(attn_kernel, cudaFuncAttributeMaxDynamicSharedMemorySize, ASMEM);

    // fused QKV projections; outputs rounded to tf32 for attention consumption
    gemm_nt<<<dim3(DDIM / GBN, MTOT / GBM, 3), 256, GSMEM>>>(
        xq, xk, xv, Wq, Wk, Wv, Qp, Kp, Vp, 1);

    attn_kernel<<<dim3(SS / AQT, BB * HH), ATHR, ASMEM>>>(Qp, Kp, Vp, mask, Ap);

    // output projection; exact fp32 output
    gemm_nt<<<dim3(DDIM / GBN, MTOT / GBM, 1), 256, GSMEM>>>(
        Ap, Ap, Ap, Wo, Wo, Wo, out, out, out, 0);
}